// round 8
// baseline (speedup 1.0000x reference)
#include <cuda_runtime.h>
#include <cuda_bf16.h>
#include <cstdint>

// Problem constants
#define BB 2
#define NN 2048
#define DDIM 1024
#define HH 16
#define HD 64
#define MROWS (BB * NN)   // 4096
#define N3D (3 * DDIM)    // 3072

// ---------------------------------------------------------------------------
// Scratch (no allocations allowed)
// ---------------------------------------------------------------------------
__device__ __align__(128) float g_qkv[MROWS * N3D];    // [4096, 3072]
__device__ __align__(128) float g_ao[MROWS * DDIM];    // [4096, 1024]
// attn bf16 buffers
__device__ __align__(128) __nv_bfloat16 g_ahi[MROWS * DDIM];   // q hi (head-major)
__device__ __align__(128) __nv_bfloat16 g_alo[MROWS * DDIM];   // q lo
__device__ __align__(128) __nv_bfloat16 g_aohi[MROWS * DDIM];  // k hi
__device__ __align__(128) __nv_bfloat16 g_aolo[MROWS * DDIM];  // k lo
__device__ __align__(128) __nv_bfloat16 g_vth[MROWS * DDIM];   // V^T hi [bh][64][2048]
__device__ __align__(128) __nv_bfloat16 g_vtl[MROWS * DDIM];   // V^T lo
// int8 GEMM operands
__device__ __align__(128) char  g_ai1[MROWS * DDIM];
__device__ __align__(128) char  g_ai2[MROWS * DDIM];
__device__ __align__(128) float g_sa[MROWS];
__device__ __align__(128) char  g_wq1[N3D * DDIM];
__device__ __align__(128) char  g_wq2[N3D * DDIM];
__device__ __align__(128) float g_sbq[N3D];
__device__ __align__(128) char  g_wp1[DDIM * DDIM];
__device__ __align__(128) char  g_wp2[DDIM * DDIM];
__device__ __align__(128) float g_sbp[DDIM];

// ---------------------------------------------------------------------------
// Baseline-PTX tensor-core helpers
// ---------------------------------------------------------------------------
__device__ __forceinline__ uint32_t smem_u32(const void* p) {
    uint32_t a;
    asm("{ .reg .u64 t; cvta.to.shared.u64 t, %1; cvt.u32.u64 %0, t; }"
        : "=r"(a) : "l"(p));
    return a;
}
__device__ __forceinline__ void ldsm4(uint32_t r[4], uint32_t addr) {
    asm volatile("ldmatrix.sync.aligned.m8n8.x4.shared.b16 {%0,%1,%2,%3}, [%4];"
                 : "=r"(r[0]), "=r"(r[1]), "=r"(r[2]), "=r"(r[3]) : "r"(addr));
}
__device__ __forceinline__ void mma16816(float c[4], const uint32_t a[4],
                                         uint32_t b0, uint32_t b1) {
    asm volatile(
        "mma.sync.aligned.m16n8k16.row.col.f32.bf16.bf16.f32 "
        "{%0,%1,%2,%3}, {%4,%5,%6,%7}, {%8,%9}, {%0,%1,%2,%3};"
        : "+f"(c[0]), "+f"(c[1]), "+f"(c[2]), "+f"(c[3])
        : "r"(a[0]), "r"(a[1]), "r"(a[2]), "r"(a[3]), "r"(b0), "r"(b1));
}
__device__ __forceinline__ void mma_i8(int c[4], const uint32_t a[4],
                                       uint32_t b0, uint32_t b1) {
    asm volatile(
        "mma.sync.aligned.m16n8k32.row.col.s32.s8.s8.s32 "
        "{%0,%1,%2,%3}, {%4,%5,%6,%7}, {%8,%9}, {%0,%1,%2,%3};"
        : "+r"(c[0]), "+r"(c[1]), "+r"(c[2]), "+r"(c[3])
        : "r"(a[0]), "r"(a[1]), "r"(a[2]), "r"(a[3]), "r"(b0), "r"(b1));
}
__device__ __forceinline__ void cp16(uint32_t dst, const void* src) {
    asm volatile("cp.async.cg.shared.global [%0], [%1], 16;"
                 :: "r"(dst), "l"(src) : "memory");
}
#define CP_COMMIT() asm volatile("cp.async.commit_group;" ::: "memory")
#define CP_WAIT1()  asm volatile("cp.async.wait_group 1;" ::: "memory")

__device__ __forceinline__ uint32_t packbf(float x, float y) {
    __nv_bfloat162 t = __floats2bfloat162_rn(x, y);
    return *(uint32_t*)&t;
}

// ---------------------------------------------------------------------------
// Row-wise 2-slice int8 quantization: x[row][1024] -> q1,q2 int8, srow scale.
// One CTA (256 threads) per row.
// ---------------------------------------------------------------------------
__global__ __launch_bounds__(256) void rowquant(const float* __restrict__ x,
                                                char* __restrict__ q1,
                                                char* __restrict__ q2,
                                                float* __restrict__ srow) {
    __shared__ float wmx[8];
    const int row = blockIdx.x;
    const int tid = threadIdx.x;
    float4 v = ((const float4*)(x + (size_t)row * 1024))[tid];
    float m = fmaxf(fmaxf(fabsf(v.x), fabsf(v.y)), fmaxf(fabsf(v.z), fabsf(v.w)));
    #pragma unroll
    for (int off = 16; off >= 1; off >>= 1)
        m = fmaxf(m, __shfl_xor_sync(0xffffffffu, m, off));
    if ((tid & 31) == 0) wmx[tid >> 5] = m;
    __syncthreads();
    float rmax = wmx[0];
    #pragma unroll
    for (int i = 1; i < 8; i++) rmax = fmaxf(rmax, wmx[i]);
    if (tid == 0) srow[row] = rmax * (1.0f / 127.0f);
    float inv = rmax > 0.f ? 127.0f / rmax : 0.f;

    float a[4] = {v.x, v.y, v.z, v.w};
    char c1[4], c2[4];
    #pragma unroll
    for (int j = 0; j < 4; j++) {
        float u = a[j] * inv;
        int i1 = __float2int_rn(u);
        int i2 = __float2int_rn((u - (float)i1) * 128.0f);
        c1[j] = (char)i1;
        c2[j] = (char)i2;
    }
    ((char4*)q1)[(size_t)row * 256 + tid] = make_char4(c1[0], c1[1], c1[2], c1[3]);
    ((char4*)q2)[(size_t)row * 256 + tid] = make_char4(c2[0], c2[1], c2[2], c2[3]);
}

// Column abs-max of W[1024][N] -> sB[col] = max/127
__global__ __launch_bounds__(256) void colmax(const float* __restrict__ W,
                                              float* __restrict__ sB, int N) {
    const int col = blockIdx.x * 256 + threadIdx.x;
    float m = 0.f;
    #pragma unroll 4
    for (int k = 0; k < 1024; k++)
        m = fmaxf(m, fabsf(W[(size_t)k * N + col]));
    sB[col] = m * (1.0f / 127.0f);
}

// Transpose + 2-slice int8 quant: W[K=1024][N] -> q1,q2 [N][1024]
__global__ __launch_bounds__(256) void transpose_quant(const float* __restrict__ W,
                                                       char* __restrict__ q1,
                                                       char* __restrict__ q2,
                                                       const float* __restrict__ sB,
                                                       int N) {
    __shared__ float t[32][33];
    int n0 = blockIdx.x * 32, k0 = blockIdx.y * 32;
    int tx = threadIdx.x, ty = threadIdx.y;  // 32 x 8
    #pragma unroll
    for (int i = 0; i < 4; i++)
        t[ty + i * 8][tx] = W[(size_t)(k0 + ty + i * 8) * N + n0 + tx];
    __syncthreads();
    #pragma unroll
    for (int i = 0; i < 4; i++) {
        int r = ty + i * 8;
        float s = sB[n0 + r];
        float inv = s > 0.f ? 1.0f / s : 0.f;
        float u = t[tx][r] * inv;
        int i1 = __float2int_rn(u);
        int i2 = __float2int_rn((u - (float)i1) * 128.0f);
        size_t oi = (size_t)(n0 + r) * 1024 + k0 + tx;
        q1[oi] = (char)i1;
        q2[oi] = (char)i2;
    }
}

// ---------------------------------------------------------------------------
// Q/K repack: g_qkv -> head-major [bh][n][64] bf16 hi/lo. Q scaled by 0.125.
// ---------------------------------------------------------------------------
__global__ __launch_bounds__(256) void qk_split(
    __nv_bfloat16* __restrict__ qh, __nv_bfloat16* __restrict__ ql,
    __nv_bfloat16* __restrict__ kh, __nv_bfloat16* __restrict__ kl) {
    int i = blockIdx.x * blockDim.x + threadIdx.x;
    if (i >= MROWS * DDIM / 4) return;
    int row = i >> 8;
    int c4  = i & 255;
    int h   = c4 >> 4;
    int d   = (c4 & 15) * 4;
    int b = row >> 11, n = row & 2047;
    size_t oi = ((size_t)(b * HH + h) * NN + n) * HD + d;

    float4 q = *(const float4*)&g_qkv[(size_t)row * N3D + c4 * 4];
    float4 k = *(const float4*)&g_qkv[(size_t)row * N3D + DDIM + c4 * 4];
    float qa[4] = {q.x * 0.125f, q.y * 0.125f, q.z * 0.125f, q.w * 0.125f};
    float ka[4] = {k.x, k.y, k.z, k.w};
    __nv_bfloat16 qhh[4], qll[4], khh[4], kll[4];
    #pragma unroll
    for (int j = 0; j < 4; j++) {
        qhh[j] = __float2bfloat16(qa[j]);
        qll[j] = __float2bfloat16(qa[j] - __bfloat162float(qhh[j]));
        khh[j] = __float2bfloat16(ka[j]);
        kll[j] = __float2bfloat16(ka[j] - __bfloat162float(khh[j]));
    }
    ((__nv_bfloat162*)(qh + oi))[0] = __nv_bfloat162(qhh[0], qhh[1]);
    ((__nv_bfloat162*)(qh + oi))[1] = __nv_bfloat162(qhh[2], qhh[3]);
    ((__nv_bfloat162*)(ql + oi))[0] = __nv_bfloat162(qll[0], qll[1]);
    ((__nv_bfloat162*)(ql + oi))[1] = __nv_bfloat162(qll[2], qll[3]);
    ((__nv_bfloat162*)(kh + oi))[0] = __nv_bfloat162(khh[0], khh[1]);
    ((__nv_bfloat162*)(kh + oi))[1] = __nv_bfloat162(khh[2], khh[3]);
    ((__nv_bfloat162*)(kl + oi))[0] = __nv_bfloat162(kll[0], kll[1]);
    ((__nv_bfloat162*)(kl + oi))[1] = __nv_bfloat162(kll[2], kll[3]);
}

// ---------------------------------------------------------------------------
// V repack transposed: g_qkv v-part -> [bh][64 d][2048 n] bf16 hi/lo
// ---------------------------------------------------------------------------
__global__ __launch_bounds__(256) void v_splitT(
    __nv_bfloat16* __restrict__ vth, __nv_bfloat16* __restrict__ vtl) {
    __shared__ float t[64][65];
    const int n0 = blockIdx.x * 64;
    const int bh = blockIdx.y;
    const int b = bh >> 4, h = bh & 15;
    const int tid = threadIdx.x;
    const int r16 = tid >> 4;
    const int c16 = tid & 15;

    #pragma unroll
    for (int i = 0; i < 4; i++) {
        int n = i * 16 + r16;
        float4 v = *(const float4*)&g_qkv[(size_t)(b * NN + n0 + n) * N3D
                                          + 2 * DDIM + h * HD + c16 * 4];
        t[n][c16 * 4 + 0] = v.x;
        t[n][c16 * 4 + 1] = v.y;
        t[n][c16 * 4 + 2] = v.z;
        t[n][c16 * 4 + 3] = v.w;
    }
    __syncthreads();
    #pragma unroll
    for (int i = 0; i < 4; i++) {
        int d = i * 16 + r16;
        int n = c16 * 4;
        __nv_bfloat16 hh[4], ll[4];
        #pragma unroll
        for (int j = 0; j < 4; j++) {
            float v = t[n + j][d];
            hh[j] = __float2bfloat16(v);
            ll[j] = __float2bfloat16(v - __bfloat162float(hh[j]));
        }
        size_t oi = ((size_t)bh * HD + d) * NN + n0 + n;
        ((__nv_bfloat162*)(vth + oi))[0] = __nv_bfloat162(hh[0], hh[1]);
        ((__nv_bfloat162*)(vth + oi))[1] = __nv_bfloat162(hh[2], hh[3]);
        ((__nv_bfloat162*)(vtl + oi))[0] = __nv_bfloat162(ll[0], ll[1]);
        ((__nv_bfloat162*)(vtl + oi))[1] = __nv_bfloat162(ll[2], ll[3]);
    }
}

// ---------------------------------------------------------------------------
// int8 Ozaki GEMM: C[M,NTOT] = sA*sB*(A1B1 + (A1B2+A2B1)/128) + bias
// A,B given as 2-slice int8, B row-major [NTOT][1024] (k-major).
// CTA 128x128, BK=32, 512 threads (16 warps, 4x4, 32x32/warp), 3-stage cp.async.
// SMEM: 4 tiles [128 rows][32B data, 48B pitch] = 24576 B/stage, x3.
// ---------------------------------------------------------------------------
#define I8_TILE  6144            // 128 * 48
#define I8_STAGE (4 * I8_TILE)   // 24576
#define I8_SMEM  (3 * I8_STAGE)  // 73728

template<int NTOT>
__global__ __launch_bounds__(512, 1) void tc_gemm_i8(
    const char* __restrict__ a1, const char* __restrict__ a2,
    const char* __restrict__ b1, const char* __restrict__ b2,
    const float* __restrict__ sA, const float* __restrict__ sB,
    const float* __restrict__ bias, float* __restrict__ C)
{
    extern __shared__ char sm[];
    const uint32_t smb = smem_u32(sm);
    const int tid = threadIdx.x;
    const int lane = tid & 31;
    const int wid = tid >> 5;
    const int wm = wid & 3;       // row quarter (32 rows)
    const int wn = wid >> 2;      // col quarter (32 cols)
    const int bm = blockIdx.y * 128;
    const int bn = blockIdx.x * 128;

    int acc0[2][4][4], acc1[2][4][4];
    #pragma unroll
    for (int i = 0; i < 2; i++)
        #pragma unroll
        for (int j = 0; j < 4; j++)
            #pragma unroll
            for (int k = 0; k < 4; k++) { acc0[i][j][k] = 0; acc1[i][j][k] = 0; }

    // loader: 1024 16B-chunks per stage, 2 per thread
    // chunk n: tile = n>>8, row = (n>>1)&127, c = n&1
    #define I8_LOAD(stg, k0)                                                      \
        do {                                                                      \
            uint32_t st_ = smb + (stg) * I8_STAGE;                                \
            _Pragma("unroll")                                                     \
            for (int j_ = 0; j_ < 2; j_++) {                                      \
                int n_ = tid * 2 + j_;                                            \
                int tile_ = n_ >> 8, row_ = (n_ >> 1) & 127, c_ = n_ & 1;         \
                uint32_t dst_ = st_ + tile_ * I8_TILE + row_ * 48 + c_ * 16;      \
                const char* src_;                                                 \
                if (tile_ == 0)      src_ = a1 + (size_t)(bm + row_) * 1024;      \
                else if (tile_ == 1) src_ = a2 + (size_t)(bm + row_) * 1024;      \
                else if (tile_ == 2) src_ = b1 + (size_t)(bn + row_) * 1024;      \
                else                 src_ = b2 + (size_t)(bn + row_) * 1024;      \
                cp16(dst_, src_ + (k0) + c_ * 16);                                \
            }                                                                     \
        } while (0)

    I8_LOAD(0, 0);
    CP_COMMIT();
    I8_LOAD(1, 32);
    CP_COMMIT();

    const int NIT = 1024 / 32;  // 32
    int stg = 0;
    for (int it = 0; it < NIT; it++) {
        CP_WAIT1();
        __syncthreads();
        if (it + 2 < NIT) I8_LOAD((stg + 2) % 3, (it + 2) * 32);
        CP_COMMIT();

        const char* pA1 = sm + stg * I8_STAGE;
        const char* pA2 = pA1 + I8_TILE;
        const char* pB1 = pA1 + 2 * I8_TILE;
        const char* pB2 = pA1 + 3 * I8_TILE;

        uint32_t af1[2][4], af2[2][4];
        #pragma unroll
        for (int mf = 0; mf < 2; mf++) {
            int o = (wm * 32 + mf * 16 + (lane >> 2)) * 48 + 4 * (lane & 3);
            af1[mf][0] = *(const uint32_t*)(pA1 + o);
            af1[mf][1] = *(const uint32_t*)(pA1 + o + 384);
            af1[mf][2] = *(const uint32_t*)(pA1 + o + 16);
            af1[mf][3] = *(const uint32_t*)(pA1 + o + 400);
            af2[mf][0] = *(const uint32_t*)(pA2 + o);
            af2[mf][1] = *(const uint32_t*)(pA2 + o + 384);
            af2[mf][2] = *(const uint32_t*)(pA2 + o + 16);
            af2[mf][3] = *(const uint32_t*)(pA2 + o + 400);
        }
        #pragma unroll
        for (int nf = 0; nf < 4; nf++) {
            int o = (wn * 32 + nf * 8 + (lane >> 2)) * 48 + 4 * (lane & 3);
            uint32_t b10 = *(const uint32_t*)(pB1 + o);
            uint32_t b11 = *(const uint32_t*)(pB1 + o + 16);
            uint32_t b20 = *(const uint32_t*)(pB2 + o);
            uint32_t b21 = *(const uint32_t*)(pB2 + o + 16);
            #pragma unroll
            for (int mf = 0; mf < 2; mf++) {
                mma_i8(acc0[mf][nf], af1[mf], b10, b11);
                mma_i8(acc1[mf][nf], af1[mf], b20, b21);
                mma_i8(acc1[mf][nf], af2[mf], b10, b11);
            }
        }
        stg = (stg + 1) % 3;
    }

    // Dequant epilogue
    #pragma unroll
    for (int nf = 0; nf < 4; nf++) {
        int col = bn + wn * 32 + nf * 8 + (lane & 3) * 2;
        float sb0 = __ldg(&sB[col]),  sb1 = __ldg(&sB[col + 1]);
        float bi0 = __ldg(&bias[col]), bi1 = __ldg(&bias[col + 1]);
        #pragma unroll
        for (int mf = 0; mf < 2; mf++) {
            int row0 = bm + wm * 32 + mf * 16 + (lane >> 2);
            float sa0 = __ldg(&sA[row0]), sa1 = __ldg(&sA[row0 + 8]);
            float2 v0, v1;
            v0.x = sa0 * sb0 * ((float)acc0[mf][nf][0] + 0.0078125f * (float)acc1[mf][nf][0]) + bi0;
            v0.y = sa0 * sb1 * ((float)acc0[mf][nf][1] + 0.0078125f * (float)acc1[mf][nf][1]) + bi1;
            v1.x = sa1 * sb0 * ((float)acc0[mf][nf][2] + 0.0078125f * (float)acc1[mf][nf][2]) + bi0;
            v1.y = sa1 * sb1 * ((float)acc0[mf][nf][3] + 0.0078125f * (float)acc1[mf][nf][3]) + bi1;
            *(float2*)&C[(size_t)row0 * NTOT + col]       = v0;
            *(float2*)&C[(size_t)(row0 + 8) * NTOT + col] = v1;
        }
    }
}

// ---------------------------------------------------------------------------
// Flash attention via mma.sync, bf16x3 split (unchanged, passing)
// ---------------------------------------------------------------------------
#define AT_KSTR 72
#define AT_VSTR 136
#define ATT_SMEM ((2 * 128 * AT_KSTR + 2 * 64 * AT_VSTR) * 2)  // 71680

__global__ __launch_bounds__(256, 1) void attn_mma(
    const __nv_bfloat16* __restrict__ qh, const __nv_bfloat16* __restrict__ ql,
    const __nv_bfloat16* __restrict__ kh, const __nv_bfloat16* __restrict__ kl,
    const __nv_bfloat16* __restrict__ vth, const __nv_bfloat16* __restrict__ vtl)
{
    extern __shared__ __nv_bfloat16 sb[];
    __nv_bfloat16* sKh = sb;
    __nv_bfloat16* sKl = sb + 128 * AT_KSTR;
    __nv_bfloat16* sVh = sb + 2 * 128 * AT_KSTR;
    __nv_bfloat16* sVl = sVh + 64 * AT_VSTR;
    const uint32_t aKh = smem_u32(sKh), aKl = smem_u32(sKl);
    const uint32_t aVh = smem_u32(sVh), aVl = smem_u32(sVl);

    const int tid = threadIdx.x, lane = tid & 31, w = tid >> 5;
    const int qt = 15 - (int)blockIdx.x;
    const int bh = blockIdx.y;
    const int b = bh >> 4, h = bh & 15;
    const size_t hb = (size_t)bh * (NN * HD);
    const size_t vb = (size_t)bh * (HD * NN);

    const int r8  = tid >> 3, c8 = tid & 7;
    const int r16v = tid >> 4, c16v = tid & 15;
    const uint32_t brow = (uint32_t)((lane & 7) | ((lane & 16) >> 1));
    const uint32_t bcol8 = (uint32_t)(((lane >> 3) & 1) * 8);

    #pragma unroll
    for (int i = 0; i < 4; i++) {
        int r = i * 32 + r8;
        size_t g = hb + (size_t)(qt * 128 + r) * HD + c8 * 8;
        *(uint4*)(sKh + r * AT_KSTR + c8 * 8) = *(const uint4*)(qh + g);
        *(uint4*)(sKl + r * AT_KSTR + c8 * 8) = *(const uint4*)(ql + g);
    }
    __syncthreads();
    uint32_t qfh[4][4], qfl[4][4];
    #pragma unroll
    for (int ks = 0; ks < 4; ks++) {
        uint32_t off = (uint32_t)(((w * 16 + (lane & 15)) * AT_KSTR
                                   + (lane >> 4) * 8 + ks * 16) * 2);
        ldsm4(qfh[ks], aKh + off);
        ldsm4(qfl[ks], aKl + off);
    }

    float m0 = -1e30f, m1 = -1e30f, l0 = 0.f, l1 = 0.f;
    float o[8][4];
    #pragma unroll
    for (int i = 0; i < 8; i++)
        #pragma unroll
        for (int j = 0; j < 4; j++) o[i][j] = 0.f;

    const int nkv = qt + 1;
    for (int kt = 0; kt < nkv; kt++) {
        __syncthreads();
        const int kv0 = kt * 128;
        #pragma unroll
        for (int i = 0; i < 4; i++) {
            int r = i * 32 + r8;
            size_t g = hb + (size_t)(kv0 + r) * HD + c8 * 8;
            *(uint4*)(sKh + r * AT_KSTR + c8 * 8) = *(const uint4*)(kh + g);
            *(uint4*)(sKl + r * AT_KSTR + c8 * 8) = *(const uint4*)(kl + g);
        }
        #pragma unroll
        for (int i = 0; i < 4; i++) {
            int d = i * 16 + r16v;
            size_t g = vb + (size_t)d * NN + kv0 + c16v * 8;
            *(uint4*)(sVh + d * AT_VSTR + c16v * 8) = *(const uint4*)(vth + g);
            *(uint4*)(sVl + d * AT_VSTR + c16v * 8) = *(const uint4*)(vtl + g);
        }
        __syncthreads();

        float s[16][4];
        #pragma unroll
        for (int i = 0; i < 16; i++)
            #pragma unroll
            for (int j = 0; j < 4; j++) s[i][j] = 0.f;

        #pragma unroll
        for (int g = 0; g < 8; g++) {
            #pragma unroll
            for (int ks = 0; ks < 4; ks++) {
                uint32_t bhf[4], blf[4];
                uint32_t off = (uint32_t)((((g * 16) + brow) * AT_KSTR
                                           + bcol8 + ks * 16) * 2);
                ldsm4(bhf, aKh + off);
                ldsm4(blf, aKl + off);
                #pragma unroll
                for (int nf2 = 0; nf2 < 2; nf2++) {
                    int nf = g * 2 + nf2, oo = nf2 * 2;
                    mma16816(s[nf], qfh[ks], bhf[oo], bhf[oo + 1]);
                    mma16816(s[nf], qfh[ks], blf[oo], blf[oo + 1]);
                    mma16816(s[nf], qfl[ks], bhf[oo], bhf[oo + 1]);
                }
            }
        }

        if (kt == qt) {
            int row0 = w * 16 + (lane >> 2);
            #pragma unroll
            for (int nf = 0; nf < 16; nf++) {
                int col = nf * 8 + (lane & 3) * 2;
                if (col > row0)     s[nf][0] = -1e30f;
                if (col + 1 > row0) s[nf][1] = -1e30f;
                if (col > row0 + 8)     s[nf][2] = -1e30f;
                if (col + 1 > row0 + 8) s[nf][3] = -1e30f;
            }
        }

        float mt0 = -1e30f, mt1 = -1e30f;
        #pragma unroll
        for (int nf = 0; nf < 16; nf++) {
            mt0 = fmaxf(mt0, fmaxf(s[nf][0], s[nf][1]));
            mt1 = fmaxf(mt1, fmaxf(s[nf][2], s[nf][3]));
        }
        mt0 = fmaxf(mt0, __shfl_xor_sync(0xffffffffu, mt0, 1));
        mt0 = fmaxf(mt0, __shfl_xor_sync(0xffffffffu, mt0, 2));
        mt1 = fmaxf(mt1, __shfl_xor_sync(0xffffffffu, mt1, 1));
        mt1 = fmaxf(mt1, __shfl_xor_sync(0xffffffffu, mt1, 2));
        float mn0 = fmaxf(m0, mt0), mn1 = fmaxf(m1, mt1);
        float cr0 = __expf(m0 - mn0), cr1 = __expf(m1 - mn1);
        float rs0 = 0.f, rs1 = 0.f;
        #pragma unroll
        for (int nf = 0; nf < 16; nf++) {
            s[nf][0] = __expf(s[nf][0] - mn0);
            s[nf][1] = __expf(s[nf][1] - mn0);
            s[nf][2] = __expf(s[nf][2] - mn1);
            s[nf][3] = __expf(s[nf][3] - mn1);
            rs0 += s[nf][0] + s[nf][1];
            rs1 += s[nf][2] + s[nf][3];
        }
        rs0 += __shfl_xor_sync(0xffffffffu, rs0, 1);
        rs0 += __shfl_xor_sync(0xffffffffu, rs0, 2);
        rs1 += __shfl_xor_sync(0xffffffffu, rs1, 1);
        rs1 += __shfl_xor_sync(0xffffffffu, rs1, 2);
        l0 = l0 * cr0 + rs0;
        l1 = l1 * cr1 + rs1;
        m0 = mn0; m1 = mn1;
        #pragma unroll
        for (int nf = 0; nf < 8; nf++) {
            o[nf][0] *= cr0; o[nf][1] *= cr0;
            o[nf][2] *= cr1; o[nf][3] *= cr1;
        }

        #pragma unroll
        for (int ks2 = 0; ks2 < 8; ks2++) {
            uint32_t pah[4], pal[4];
            {
                const float* s0 = s[2 * ks2];
                const float* s1 = s[2 * ks2 + 1];
                float h00 = __bfloat162float(__float2bfloat16(s0[0]));
                float h01 = __bfloat162float(__float2bfloat16(s0[1]));
                float h02 = __bfloat162float(__float2bfloat16(s0[2]));
                float h03 = __bfloat162float(__float2bfloat16(s0[3]));
                float h10 = __bfloat162float(__float2bfloat16(s1[0]));
                float h11 = __bfloat162float(__float2bfloat16(s1[1]));
                float h12 = __bfloat162float(__float2bfloat16(s1[2]));
                float h13 = __bfloat162float(__float2bfloat16(s1[3]));
                pah[0] = packbf(h00, h01);
                pah[1] = packbf(h02, h03);
                pah[2] = packbf(h10, h11);
                pah[3] = packbf(h12, h13);
                pal[0] = packbf(s0[0] - h00, s0[1] - h01);
                pal[1] = packbf(s0[2] - h02, s0[3] - h03);
                pal[2] = packbf(s1[0] - h10, s1[1] - h11);
                pal[3] = packbf(s1[2] - h12, s1[3] - h13);
            }
            #pragma unroll
            for (int g = 0; g < 4; g++) {
                uint32_t vhf[4], vlf[4];
                uint32_t off = (uint32_t)((((g * 16) + brow) * AT_VSTR
                                           + bcol8 + ks2 * 16) * 2);
                ldsm4(vhf, aVh + off);
                ldsm4(vlf, aVl + off);
                #pragma unroll
                for (int nf2 = 0; nf2 < 2; nf2++) {
                    int nf = g * 2 + nf2, oo = nf2 * 2;
                    mma16816(o[nf], pah, vhf[oo], vhf[oo + 1]);
                    mma16816(o[nf], pah, vlf[oo], vlf[oo + 1]);
                    mma16816(o[nf], pal, vhf[oo], vhf[oo + 1]);
                }
            }
        }
    }

    float inv0 = 1.f / l0, inv1 = 1.f / l1;
    const int row0 = b * NN + qt * 128 + w * 16 + (lane >> 2);
    #pragma unroll
    for (int nf = 0; nf < 8; nf++) {
        int col = h * HD + nf * 8 + (lane & 3) * 2;
        *(float2*)&g_ao[(size_t)row0 * DDIM + col] =
            make_float2(o[nf][0] * inv0, o[nf][1] * inv0);
        *(float2*)&g_ao[(size_t)(row0 + 8) * DDIM + col] =
            make_float2(o[nf][2] * inv1, o[nf][3] * inv1);
    }
}

// ---------------------------------------------------------------------------
// Launch
// ---------------------------------------------------------------------------
extern "C" void kernel_launch(void* const* d_in, const int* in_sizes, int n_in,
                              void* d_out, int out_size) {
    const float* hs     = (const float*)d_in[0];
    const float* W_attn = (const float*)d_in[1];
    const float* b_attn = (const float*)d_in[2];
    const float* W_proj = (const float*)d_in[3];
    const float* b_proj = (const float*)d_in[4];
    float* out = (float*)d_out;

    cudaFuncSetAttribute(attn_mma,
                         cudaFuncAttributeMaxDynamicSharedMemorySize, ATT_SMEM);
    cudaFuncSetAttribute(tc_gemm_i8<N3D>,
                         cudaFuncAttributeMaxDynamicSharedMemorySize, I8_SMEM);
    cudaFuncSetAttribute(tc_gemm_i8<DDIM>,
                         cudaFuncAttributeMaxDynamicSharedMemorySize, I8_SMEM);

    __nv_bfloat16 *ahi, *alo, *aohi, *aolo, *vth, *vtl;
    char *ai1, *ai2, *wq1, *wq2, *wp1, *wp2;
    float *sa, *sbq, *sbp, *qkv_p, *ao_p;
    cudaGetSymbolAddress((void**)&ahi,  g_ahi);
    cudaGetSymbolAddress((void**)&alo,  g_alo);
    cudaGetSymbolAddress((void**)&aohi, g_aohi);
    cudaGetSymbolAddress((void**)&aolo, g_aolo);
    cudaGetSymbolAddress((void**)&vth,  g_vth);
    cudaGetSymbolAddress((void**)&vtl,  g_vtl);
    cudaGetSymbolAddress((void**)&ai1,  g_ai1);
    cudaGetSymbolAddress((void**)&ai2,  g_ai2);
    cudaGetSymbolAddress((void**)&sa,   g_sa);
    cudaGetSymbolAddress((void**)&wq1,  g_wq1);
    cudaGetSymbolAddress((void**)&wq2,  g_wq2);
    cudaGetSymbolAddress((void**)&sbq,  g_sbq);
    cudaGetSymbolAddress((void**)&wp1,  g_wp1);
    cudaGetSymbolAddress((void**)&wp2,  g_wp2);
    cudaGetSymbolAddress((void**)&sbp,  g_sbp);
    cudaGetSymbolAddress((void**)&qkv_p, g_qkv);
    cudaGetSymbolAddress((void**)&ao_p,  g_ao);

    dim3 tt(32, 8);
    // 1) quantize hidden_states rows
    rowquant<<<MROWS, 256>>>(hs, ai1, ai2, sa);
    // 2) weight scales + transposed int8 slices
    colmax<<<N3D / 256, 256>>>(W_attn, sbq, N3D);
    transpose_quant<<<dim3(N3D / 32, DDIM / 32), tt>>>(W_attn, wq1, wq2, sbq, N3D);
    colmax<<<DDIM / 256, 256>>>(W_proj, sbp, DDIM);
    transpose_quant<<<dim3(DDIM / 32, DDIM / 32), tt>>>(W_proj, wp1, wp2, sbp, DDIM);
    // 3) QKV projection (int8 tensor cores)
    tc_gemm_i8<N3D><<<dim3(N3D / 128, MROWS / 128), 512, I8_SMEM>>>(
        ai1, ai2, wq1, wq2, sa, sbq, b_attn, qkv_p);
    // 4) repack q/k (head-major, q pre-scaled) and v (transposed)
    qk_split<<<(MROWS * DDIM / 4 + 255) / 256, 256>>>(ahi, alo, aohi, aolo);
    v_splitT<<<dim3(NN / 64, BB * HH), 256>>>(vth, vtl);
    // 5) causal flash attention on tensor cores (bf16x3)
    attn_mma<<<dim3(NN / 128, BB * HH), 256, ATT_SMEM>>>(ahi, alo, aohi, aolo, vth, vtl);
    // 6) quantize attention output rows
    rowquant<<<MROWS, 256>>>(ao_p, ai1, ai2, sa);
    // 7) output projection (int8 tensor cores)
    tc_gemm_i8<DDIM><<<dim3(DDIM / 128, MROWS / 128), 512, I8_SMEM>>>(
        ai1, ai2, wp1, wp2, sa, sbp, b_proj, out);
}

// round 9
// speedup vs baseline: 4.1637x; 4.1637x over previous
#include <cuda_runtime.h>
#include <cuda_bf16.h>
#include <cuda_fp16.h>
#include <cstdint>

// Problem constants
#define BB 2
#define NN 2048
#define DDIM 1024
#define HH 16
#define HD 64
#define MROWS (BB * NN)   // 4096
#define N3D (3 * DDIM)    // 3072

// ---------------------------------------------------------------------------
// Scratch (no allocations allowed)
// ---------------------------------------------------------------------------
__device__ __align__(128) float g_qkv[MROWS * N3D];    // [4096, 3072]
__device__ __align__(128) float g_ao[MROWS * DDIM];    // [4096, 1024]
// attention bf16 hi/lo buffers
__device__ __align__(128) __nv_bfloat16 g_ahi[MROWS * DDIM];   // q hi (head-major)
__device__ __align__(128) __nv_bfloat16 g_alo[MROWS * DDIM];   // q lo
__device__ __align__(128) __nv_bfloat16 g_aohi[MROWS * DDIM];  // k hi
__device__ __align__(128) __nv_bfloat16 g_aolo[MROWS * DDIM];  // k lo
__device__ __align__(128) __nv_bfloat16 g_vth[MROWS * DDIM];   // V^T hi [bh][64][2048]
__device__ __align__(128) __nv_bfloat16 g_vtl[MROWS * DDIM];   // V^T lo
// fp16 GEMM operands
__device__ __align__(128) __half g_ah[MROWS * DDIM];           // activations fp16
__device__ __align__(128) __half g_wqt[N3D * DDIM];            // W_attn^T fp16 [N][K]
__device__ __align__(128) __half g_wpt[DDIM * DDIM];           // W_proj^T fp16 [N][K]

// ---------------------------------------------------------------------------
// Baseline-PTX tensor-core helpers
// ---------------------------------------------------------------------------
__device__ __forceinline__ uint32_t smem_u32(const void* p) {
    uint32_t a;
    asm("{ .reg .u64 t; cvta.to.shared.u64 t, %1; cvt.u32.u64 %0, t; }"
        : "=r"(a) : "l"(p));
    return a;
}
__device__ __forceinline__ void ldsm4(uint32_t r[4], uint32_t addr) {
    asm volatile("ldmatrix.sync.aligned.m8n8.x4.shared.b16 {%0,%1,%2,%3}, [%4];"
                 : "=r"(r[0]), "=r"(r[1]), "=r"(r[2]), "=r"(r[3]) : "r"(addr));
}
// bf16 MMA (attention)
__device__ __forceinline__ void mma16816(float c[4], const uint32_t a[4],
                                         uint32_t b0, uint32_t b1) {
    asm volatile(
        "mma.sync.aligned.m16n8k16.row.col.f32.bf16.bf16.f32 "
        "{%0,%1,%2,%3}, {%4,%5,%6,%7}, {%8,%9}, {%0,%1,%2,%3};"
        : "+f"(c[0]), "+f"(c[1]), "+f"(c[2]), "+f"(c[3])
        : "r"(a[0]), "r"(a[1]), "r"(a[2]), "r"(a[3]), "r"(b0), "r"(b1));
}
// fp16 MMA (projections)
__device__ __forceinline__ void mma16816h(float c[4], const uint32_t a[4],
                                          uint32_t b0, uint32_t b1) {
    asm volatile(
        "mma.sync.aligned.m16n8k16.row.col.f32.f16.f16.f32 "
        "{%0,%1,%2,%3}, {%4,%5,%6,%7}, {%8,%9}, {%0,%1,%2,%3};"
        : "+f"(c[0]), "+f"(c[1]), "+f"(c[2]), "+f"(c[3])
        : "r"(a[0]), "r"(a[1]), "r"(a[2]), "r"(a[3]), "r"(b0), "r"(b1));
}
__device__ __forceinline__ void cp16(uint32_t dst, const void* src) {
    asm volatile("cp.async.cg.shared.global [%0], [%1], 16;"
                 :: "r"(dst), "l"(src) : "memory");
}
#define CP_COMMIT() asm volatile("cp.async.commit_group;" ::: "memory")
#define CP_WAIT1()  asm volatile("cp.async.wait_group 1;" ::: "memory")

__device__ __forceinline__ uint32_t packbf(float x, float y) {
    __nv_bfloat162 t = __floats2bfloat162_rn(x, y);
    return *(uint32_t*)&t;
}

// ---------------------------------------------------------------------------
// fp32 -> fp16 convert (elementwise, vectorized)
// ---------------------------------------------------------------------------
__global__ __launch_bounds__(256) void conv_half(const float* __restrict__ x,
                                                 __half* __restrict__ o, int n4) {
    int i = blockIdx.x * blockDim.x + threadIdx.x;
    if (i >= n4) return;
    float4 v = ((const float4*)x)[i];
    __half2 h0 = __floats2half2_rn(v.x, v.y);
    __half2 h1 = __floats2half2_rn(v.z, v.w);
    ((__half2*)o)[2 * i]     = h0;
    ((__half2*)o)[2 * i + 1] = h1;
}

// Transpose W[K,N] -> out[N,K] fp16
__global__ __launch_bounds__(256) void transpose_half(const float* __restrict__ W,
                                                      __half* __restrict__ T,
                                                      int K, int N) {
    __shared__ float t[32][33];
    int n0 = blockIdx.x * 32, k0 = blockIdx.y * 32;
    int tx = threadIdx.x, ty = threadIdx.y;  // 32 x 8
    #pragma unroll
    for (int i = 0; i < 4; i++)
        t[ty + i * 8][tx] = W[(size_t)(k0 + ty + i * 8) * N + n0 + tx];
    __syncthreads();
    #pragma unroll
    for (int i = 0; i < 4; i++) {
        int r = ty + i * 8;
        T[(size_t)(n0 + r) * K + k0 + tx] = __float2half_rn(t[tx][r]);
    }
}

// ---------------------------------------------------------------------------
// Q/K repack: g_qkv -> head-major [bh][n][64] bf16 hi/lo. Q scaled by 0.125.
// ---------------------------------------------------------------------------
__global__ __launch_bounds__(256) void qk_split(
    __nv_bfloat16* __restrict__ qh, __nv_bfloat16* __restrict__ ql,
    __nv_bfloat16* __restrict__ kh, __nv_bfloat16* __restrict__ kl) {
    int i = blockIdx.x * blockDim.x + threadIdx.x;
    if (i >= MROWS * DDIM / 4) return;
    int row = i >> 8;
    int c4  = i & 255;
    int h   = c4 >> 4;
    int d   = (c4 & 15) * 4;
    int b = row >> 11, n = row & 2047;
    size_t oi = ((size_t)(b * HH + h) * NN + n) * HD + d;

    float4 q = *(const float4*)&g_qkv[(size_t)row * N3D + c4 * 4];
    float4 k = *(const float4*)&g_qkv[(size_t)row * N3D + DDIM + c4 * 4];
    float qa[4] = {q.x * 0.125f, q.y * 0.125f, q.z * 0.125f, q.w * 0.125f};
    float ka[4] = {k.x, k.y, k.z, k.w};
    __nv_bfloat16 qhh[4], qll[4], khh[4], kll[4];
    #pragma unroll
    for (int j = 0; j < 4; j++) {
        qhh[j] = __float2bfloat16(qa[j]);
        qll[j] = __float2bfloat16(qa[j] - __bfloat162float(qhh[j]));
        khh[j] = __float2bfloat16(ka[j]);
        kll[j] = __float2bfloat16(ka[j] - __bfloat162float(khh[j]));
    }
    ((__nv_bfloat162*)(qh + oi))[0] = __nv_bfloat162(qhh[0], qhh[1]);
    ((__nv_bfloat162*)(qh + oi))[1] = __nv_bfloat162(qhh[2], qhh[3]);
    ((__nv_bfloat162*)(ql + oi))[0] = __nv_bfloat162(qll[0], qll[1]);
    ((__nv_bfloat162*)(ql + oi))[1] = __nv_bfloat162(qll[2], qll[3]);
    ((__nv_bfloat162*)(kh + oi))[0] = __nv_bfloat162(khh[0], khh[1]);
    ((__nv_bfloat162*)(kh + oi))[1] = __nv_bfloat162(khh[2], khh[3]);
    ((__nv_bfloat162*)(kl + oi))[0] = __nv_bfloat162(kll[0], kll[1]);
    ((__nv_bfloat162*)(kl + oi))[1] = __nv_bfloat162(kll[2], kll[3]);
}

// ---------------------------------------------------------------------------
// V repack transposed: g_qkv v-part -> [bh][64 d][2048 n] bf16 hi/lo
// ---------------------------------------------------------------------------
__global__ __launch_bounds__(256) void v_splitT(
    __nv_bfloat16* __restrict__ vth, __nv_bfloat16* __restrict__ vtl) {
    __shared__ float t[64][65];
    const int n0 = blockIdx.x * 64;
    const int bh = blockIdx.y;
    const int b = bh >> 4, h = bh & 15;
    const int tid = threadIdx.x;
    const int r16 = tid >> 4;
    const int c16 = tid & 15;

    #pragma unroll
    for (int i = 0; i < 4; i++) {
        int n = i * 16 + r16;
        float4 v = *(const float4*)&g_qkv[(size_t)(b * NN + n0 + n) * N3D
                                          + 2 * DDIM + h * HD + c16 * 4];
        t[n][c16 * 4 + 0] = v.x;
        t[n][c16 * 4 + 1] = v.y;
        t[n][c16 * 4 + 2] = v.z;
        t[n][c16 * 4 + 3] = v.w;
    }
    __syncthreads();
    #pragma unroll
    for (int i = 0; i < 4; i++) {
        int d = i * 16 + r16;
        int n = c16 * 4;
        __nv_bfloat16 hh[4], ll[4];
        #pragma unroll
        for (int j = 0; j < 4; j++) {
            float v = t[n + j][d];
            hh[j] = __float2bfloat16(v);
            ll[j] = __float2bfloat16(v - __bfloat162float(hh[j]));
        }
        size_t oi = ((size_t)bh * HD + d) * NN + n0 + n;
        ((__nv_bfloat162*)(vth + oi))[0] = __nv_bfloat162(hh[0], hh[1]);
        ((__nv_bfloat162*)(vth + oi))[1] = __nv_bfloat162(hh[2], hh[3]);
        ((__nv_bfloat162*)(vtl + oi))[0] = __nv_bfloat162(ll[0], ll[1]);
        ((__nv_bfloat162*)(vtl + oi))[1] = __nv_bfloat162(ll[2], ll[3]);
    }
}

// ---------------------------------------------------------------------------
// fp16 single-product GEMM via mma.sync:
// C[M,NTOT] = A[M,1024] @ B^T + bias, B as [NTOT][1024] fp16 k-major.
// CTA 128x128, BK=32, 512 threads (16 warps, 4x4, 32x32/warp), 3-stage cp.async.
// SMEM: 2 tiles of [128][40] fp16 (80B pitch) = 20480 B/stage, x3 = 61440 B.
// ---------------------------------------------------------------------------
#define TILE_B    10240
#define F16_STAGE (2 * TILE_B)    // 20480
#define F16_SMEM  (3 * F16_STAGE) // 61440

template<int NTOT>
__global__ __launch_bounds__(512) void tc_gemm_f16(
    const __half* __restrict__ A, const __half* __restrict__ B,
    const float* __restrict__ bias, float* __restrict__ C)
{
    extern __shared__ char sm[];
    const uint32_t smb = smem_u32(sm);
    const int tid = threadIdx.x;
    const int lane = tid & 31;
    const int wid = tid >> 5;
    const int wm = wid & 3;       // row quarter (32 rows)
    const int wn = wid >> 2;      // col quarter (32 cols)
    const int bm = blockIdx.y * 128;
    const int bn = blockIdx.x * 128;

    float acc[2][4][4];
    #pragma unroll
    for (int i = 0; i < 2; i++)
        #pragma unroll
        for (int j = 0; j < 4; j++)
            #pragma unroll
            for (int k = 0; k < 4; k++) acc[i][j][k] = 0.f;

    const int lrow = tid >> 2;        // 0..127
    const int lc   = tid & 3;         // 16B chunk in row
    #define F16_LOAD(stg, k0)                                                     \
        do {                                                                      \
            uint32_t st_ = smb + (stg) * F16_STAGE;                               \
            uint32_t doff_ = (uint32_t)(lrow * 80 + lc * 16);                     \
            cp16(st_ + doff_,          A + (size_t)(bm + lrow) * 1024 + (k0) + lc * 8); \
            cp16(st_ + TILE_B + doff_, B + (size_t)(bn + lrow) * 1024 + (k0) + lc * 8); \
        } while (0)

    const uint32_t a_roff = (uint32_t)((wm * 32 + (lane & 15)) * 80 + (lane >> 4) * 16);
    const uint32_t b_row  = (uint32_t)((lane & 7) | ((lane & 16) >> 1));
    const uint32_t b_roff = (uint32_t)((wn * 32 + b_row) * 80 + ((lane >> 3) & 1) * 16);

    F16_LOAD(0, 0);
    CP_COMMIT();
    F16_LOAD(1, 32);
    CP_COMMIT();

    const int NIT = 1024 / 32;  // 32
    int stg = 0;
    for (int it = 0; it < NIT; it++) {
        CP_WAIT1();
        __syncthreads();
        if (it + 2 < NIT) F16_LOAD((stg + 2) % 3, (it + 2) * 32);
        CP_COMMIT();

        const uint32_t sA = smb + stg * F16_STAGE;
        const uint32_t sB = sA + TILE_B;

        #pragma unroll
        for (int ks = 0; ks < 2; ks++) {
            uint32_t af[2][4], bf_[2][4];
            uint32_t ao = a_roff + ks * 32;
            ldsm4(af[0], sA + ao);
            ldsm4(af[1], sA + ao + 16 * 80);
            uint32_t bo = b_roff + ks * 32;
            ldsm4(bf_[0], sB + bo);
            ldsm4(bf_[1], sB + bo + 16 * 80);
            #pragma unroll
            for (int mf = 0; mf < 2; mf++)
                #pragma unroll
                for (int nf = 0; nf < 4; nf++) {
                    int g = nf >> 1, o = (nf & 1) * 2;
                    mma16816h(acc[mf][nf], af[mf], bf_[g][o], bf_[g][o + 1]);
                }
        }
        stg = (stg + 1) % 3;
    }

    #pragma unroll
    for (int nf = 0; nf < 4; nf++) {
        int col = bn + wn * 32 + nf * 8 + (lane & 3) * 2;
        float b0 = __ldg(&bias[col]);
        float b1 = __ldg(&bias[col + 1]);
        #pragma unroll
        for (int mf = 0; mf < 2; mf++) {
            int row0 = bm + wm * 32 + mf * 16 + (lane >> 2);
            float2 v0 = make_float2(acc[mf][nf][0] + b0, acc[mf][nf][1] + b1);
            float2 v1 = make_float2(acc[mf][nf][2] + b0, acc[mf][nf][3] + b1);
            *(float2*)&C[(size_t)row0 * NTOT + col]       = v0;
            *(float2*)&C[(size_t)(row0 + 8) * NTOT + col] = v1;
        }
    }
}

// ---------------------------------------------------------------------------
// Flash attention via mma.sync, bf16x3 split (unchanged, passing)
// ---------------------------------------------------------------------------
#define AT_KSTR 72
#define AT_VSTR 136
#define ATT_SMEM ((2 * 128 * AT_KSTR + 2 * 64 * AT_VSTR) * 2)  // 71680

__global__ __launch_bounds__(256, 1) void attn_mma(
    const __nv_bfloat16* __restrict__ qh, const __nv_bfloat16* __restrict__ ql,
    const __nv_bfloat16* __restrict__ kh, const __nv_bfloat16* __restrict__ kl,
    const __nv_bfloat16* __restrict__ vth, const __nv_bfloat16* __restrict__ vtl)
{
    extern __shared__ __nv_bfloat16 sb[];
    __nv_bfloat16* sKh = sb;
    __nv_bfloat16* sKl = sb + 128 * AT_KSTR;
    __nv_bfloat16* sVh = sb + 2 * 128 * AT_KSTR;
    __nv_bfloat16* sVl = sVh + 64 * AT_VSTR;
    const uint32_t aKh = smem_u32(sKh), aKl = smem_u32(sKl);
    const uint32_t aVh = smem_u32(sVh), aVl = smem_u32(sVl);

    const int tid = threadIdx.x, lane = tid & 31, w = tid >> 5;
    const int qt = 15 - (int)blockIdx.x;
    const int bh = blockIdx.y;
    const int b = bh >> 4, h = bh & 15;
    const size_t hb = (size_t)bh * (NN * HD);
    const size_t vb = (size_t)bh * (HD * NN);

    const int r8  = tid >> 3, c8 = tid & 7;
    const int r16v = tid >> 4, c16v = tid & 15;
    const uint32_t brow = (uint32_t)((lane & 7) | ((lane & 16) >> 1));
    const uint32_t bcol8 = (uint32_t)(((lane >> 3) & 1) * 8);

    #pragma unroll
    for (int i = 0; i < 4; i++) {
        int r = i * 32 + r8;
        size_t g = hb + (size_t)(qt * 128 + r) * HD + c8 * 8;
        *(uint4*)(sKh + r * AT_KSTR + c8 * 8) = *(const uint4*)(qh + g);
        *(uint4*)(sKl + r * AT_KSTR + c8 * 8) = *(const uint4*)(ql + g);
    }
    __syncthreads();
    uint32_t qfh[4][4], qfl[4][4];
    #pragma unroll
    for (int ks = 0; ks < 4; ks++) {
        uint32_t off = (uint32_t)(((w * 16 + (lane & 15)) * AT_KSTR
                                   + (lane >> 4) * 8 + ks * 16) * 2);
        ldsm4(qfh[ks], aKh + off);
        ldsm4(qfl[ks], aKl + off);
    }

    float m0 = -1e30f, m1 = -1e30f, l0 = 0.f, l1 = 0.f;
    float o[8][4];
    #pragma unroll
    for (int i = 0; i < 8; i++)
        #pragma unroll
        for (int j = 0; j < 4; j++) o[i][j] = 0.f;

    const int nkv = qt + 1;
    for (int kt = 0; kt < nkv; kt++) {
        __syncthreads();
        const int kv0 = kt * 128;
        #pragma unroll
        for (int i = 0; i < 4; i++) {
            int r = i * 32 + r8;
            size_t g = hb + (size_t)(kv0 + r) * HD + c8 * 8;
            *(uint4*)(sKh + r * AT_KSTR + c8 * 8) = *(const uint4*)(kh + g);
            *(uint4*)(sKl + r * AT_KSTR + c8 * 8) = *(const uint4*)(kl + g);
        }
        #pragma unroll
        for (int i = 0; i < 4; i++) {
            int d = i * 16 + r16v;
            size_t g = vb + (size_t)d * NN + kv0 + c16v * 8;
            *(uint4*)(sVh + d * AT_VSTR + c16v * 8) = *(const uint4*)(vth + g);
            *(uint4*)(sVl + d * AT_VSTR + c16v * 8) = *(const uint4*)(vtl + g);
        }
        __syncthreads();

        float s[16][4];
        #pragma unroll
        for (int i = 0; i < 16; i++)
            #pragma unroll
            for (int j = 0; j < 4; j++) s[i][j] = 0.f;

        #pragma unroll
        for (int g = 0; g < 8; g++) {
            #pragma unroll
            for (int ks = 0; ks < 4; ks++) {
                uint32_t bhf[4], blf[4];
                uint32_t off = (uint32_t)((((g * 16) + brow) * AT_KSTR
                                           + bcol8 + ks * 16) * 2);
                ldsm4(bhf, aKh + off);
                ldsm4(blf, aKl + off);
                #pragma unroll
                for (int nf2 = 0; nf2 < 2; nf2++) {
                    int nf = g * 2 + nf2, oo = nf2 * 2;
                    mma16816(s[nf], qfh[ks], bhf[oo], bhf[oo + 1]);
                    mma16816(s[nf], qfh[ks], blf[oo], blf[oo + 1]);
                    mma16816(s[nf], qfl[ks], bhf[oo], bhf[oo + 1]);
                }
            }
        }

        if (kt == qt) {
            int row0 = w * 16 + (lane >> 2);
            #pragma unroll
            for (int nf = 0; nf < 16; nf++) {
                int col = nf * 8 + (lane & 3) * 2;
                if (col > row0)     s[nf][0] = -1e30f;
                if (col + 1 > row0) s[nf][1] = -1e30f;
                if (col > row0 + 8)     s[nf][2] = -1e30f;
                if (col + 1 > row0 + 8) s[nf][3] = -1e30f;
            }
        }

        float mt0 = -1e30f, mt1 = -1e30f;
        #pragma unroll
        for (int nf = 0; nf < 16; nf++) {
            mt0 = fmaxf(mt0, fmaxf(s[nf][0], s[nf][1]));
            mt1 = fmaxf(mt1, fmaxf(s[nf][2], s[nf][3]));
        }
        mt0 = fmaxf(mt0, __shfl_xor_sync(0xffffffffu, mt0, 1));
        mt0 = fmaxf(mt0, __shfl_xor_sync(0xffffffffu, mt0, 2));
        mt1 = fmaxf(mt1, __shfl_xor_sync(0xffffffffu, mt1, 1));
        mt1 = fmaxf(mt1, __shfl_xor_sync(0xffffffffu, mt1, 2));
        float mn0 = fmaxf(m0, mt0), mn1 = fmaxf(m1, mt1);
        float cr0 = __expf(m0 - mn0), cr1 = __expf(m1 - mn1);
        float rs0 = 0.f, rs1 = 0.f;
        #pragma unroll
        for (int nf = 0; nf < 16; nf++) {
            s[nf][0] = __expf(s[nf][0] - mn0);
            s[nf][1] = __expf(s[nf][1] - mn0);
            s[nf][2] = __expf(s[nf][2] - mn1);
            s[nf][3] = __expf(s[nf][3] - mn1);
            rs0 += s[nf][0] + s[nf][1];
            rs1 += s[nf][2] + s[nf][3];
        }
        rs0 += __shfl_xor_sync(0xffffffffu, rs0, 1);
        rs0 += __shfl_xor_sync(0xffffffffu, rs0, 2);
        rs1 += __shfl_xor_sync(0xffffffffu, rs1, 1);
        rs1 += __shfl_xor_sync(0xffffffffu, rs1, 2);
        l0 = l0 * cr0 + rs0;
        l1 = l1 * cr1 + rs1;
        m0 = mn0; m1 = mn1;
        #pragma unroll
        for (int nf = 0; nf < 8; nf++) {
            o[nf][0] *= cr0; o[nf][1] *= cr0;
            o[nf][2] *= cr1; o[nf][3] *= cr1;
        }

        #pragma unroll
        for (int ks2 = 0; ks2 < 8; ks2++) {
            uint32_t pah[4], pal[4];
            {
                const float* s0 = s[2 * ks2];
                const float* s1 = s[2 * ks2 + 1];
                float h00 = __bfloat162float(__float2bfloat16(s0[0]));
                float h01 = __bfloat162float(__float2bfloat16(s0[1]));
                float h02 = __bfloat162float(__float2bfloat16(s0[2]));
                float h03 = __bfloat162float(__float2bfloat16(s0[3]));
                float h10 = __bfloat162float(__float2bfloat16(s1[0]));
                float h11 = __bfloat162float(__float2bfloat16(s1[1]));
                float h12 = __bfloat162float(__float2bfloat16(s1[2]));
                float h13 = __bfloat162float(__float2bfloat16(s1[3]));
                pah[0] = packbf(h00, h01);
                pah[1] = packbf(h02, h03);
                pah[2] = packbf(h10, h11);
                pah[3] = packbf(h12, h13);
                pal[0] = packbf(s0[0] - h00, s0[1] - h01);
                pal[1] = packbf(s0[2] - h02, s0[3] - h03);
                pal[2] = packbf(s1[0] - h10, s1[1] - h11);
                pal[3] = packbf(s1[2] - h12, s1[3] - h13);
            }
            #pragma unroll
            for (int g = 0; g < 4; g++) {
                uint32_t vhf[4], vlf[4];
                uint32_t off = (uint32_t)((((g * 16) + brow) * AT_VSTR
                                           + bcol8 + ks2 * 16) * 2);
                ldsm4(vhf, aVh + off);
                ldsm4(vlf, aVl + off);
                #pragma unroll
                for (int nf2 = 0; nf2 < 2; nf2++) {
                    int nf = g * 2 + nf2, oo = nf2 * 2;
                    mma16816(o[nf], pah, vhf[oo], vhf[oo + 1]);
                    mma16816(o[nf], pah, vlf[oo], vlf[oo + 1]);
                    mma16816(o[nf], pal, vhf[oo], vhf[oo + 1]);
                }
            }
        }
    }

    float inv0 = 1.f / l0, inv1 = 1.f / l1;
    const int row0 = b * NN + qt * 128 + w * 16 + (lane >> 2);
    #pragma unroll
    for (int nf = 0; nf < 8; nf++) {
        int col = h * HD + nf * 8 + (lane & 3) * 2;
        *(float2*)&g_ao[(size_t)row0 * DDIM + col] =
            make_float2(o[nf][0] * inv0, o[nf][1] * inv0);
        *(float2*)&g_ao[(size_t)(row0 + 8) * DDIM + col] =
            make_float2(o[nf][2] * inv1, o[nf][3] * inv1);
    }
}

// ---------------------------------------------------------------------------
// Launch
// ---------------------------------------------------------------------------
extern "C" void kernel_launch(void* const* d_in, const int* in_sizes, int n_in,
                              void* d_out, int out_size) {
    const float* hs     = (const float*)d_in[0];
    const float* W_attn = (const float*)d_in[1];
    const float* b_attn = (const float*)d_in[2];
    const float* W_proj = (const float*)d_in[3];
    const float* b_proj = (const float*)d_in[4];
    float* out = (float*)d_out;

    cudaFuncSetAttribute(attn_mma,
                         cudaFuncAttributeMaxDynamicSharedMemorySize, ATT_SMEM);
    cudaFuncSetAttribute(tc_gemm_f16<N3D>,
                         cudaFuncAttributeMaxDynamicSharedMemorySize, F16_SMEM);
    cudaFuncSetAttribute(tc_gemm_f16<DDIM>,
                         cudaFuncAttributeMaxDynamicSharedMemorySize, F16_SMEM);

    __nv_bfloat16 *ahi, *alo, *aohi, *aolo, *vth, *vtl;
    __half *ah, *wqt, *wpt;
    float *qkv_p, *ao_p;
    cudaGetSymbolAddress((void**)&ahi,  g_ahi);
    cudaGetSymbolAddress((void**)&alo,  g_alo);
    cudaGetSymbolAddress((void**)&aohi, g_aohi);
    cudaGetSymbolAddress((void**)&aolo, g_aolo);
    cudaGetSymbolAddress((void**)&vth,  g_vth);
    cudaGetSymbolAddress((void**)&vtl,  g_vtl);
    cudaGetSymbolAddress((void**)&ah,   g_ah);
    cudaGetSymbolAddress((void**)&wqt,  g_wqt);
    cudaGetSymbolAddress((void**)&wpt,  g_wpt);
    cudaGetSymbolAddress((void**)&qkv_p, g_qkv);
    cudaGetSymbolAddress((void**)&ao_p,  g_ao);

    dim3 tt(32, 8);
    // 1) convert hidden_states to fp16
    conv_half<<<(MROWS * DDIM / 4 + 255) / 256, 256>>>(hs, ah, MROWS * DDIM / 4);
    // 2) transpose weights to fp16 [N][K]
    transpose_half<<<dim3(N3D / 32, DDIM / 32), tt>>>(W_attn, wqt, DDIM, N3D);
    transpose_half<<<dim3(DDIM / 32, DDIM / 32), tt>>>(W_proj, wpt, DDIM, DDIM);
    // 3) QKV projection (fp16 tensor cores, single product)
    tc_gemm_f16<N3D><<<dim3(N3D / 128, MROWS / 128), 512, F16_SMEM>>>(
        ah, wqt, b_attn, qkv_p);
    // 4) repack q/k (head-major, q pre-scaled) and v (transposed) for attention
    qk_split<<<(MROWS * DDIM / 4 + 255) / 256, 256>>>(ahi, alo, aohi, aolo);
    v_splitT<<<dim3(NN / 64, BB * HH), 256>>>(vth, vtl);
    // 5) causal flash attention on tensor cores (bf16x3)
    attn_mma<<<dim3(NN / 128, BB * HH), 256, ATT_SMEM>>>(ahi, alo, aohi, aolo, vth, vtl);
    // 6) convert attention output to fp16
    conv_half<<<(MROWS * DDIM / 4 + 255) / 256, 256>>>(ao_p, ah, MROWS * DDIM / 4);
    // 7) output projection (fp16 tensor cores, single product)
    tc_gemm_f16<DDIM><<<dim3(DDIM / 128, MROWS / 128), 512, F16_SMEM>>>(
        ah, wpt, b_proj, out);
}

// round 10
// speedup vs baseline: 4.2131x; 1.0119x over previous
#include <cuda_runtime.h>
#include <cuda_bf16.h>
#include <cuda_fp16.h>
#include <cstdint>

// Problem constants
#define BB 2
#define NN 2048
#define DDIM 1024
#define HH 16
#define HD 64
#define MROWS (BB * NN)   // 4096
#define N3D (3 * DDIM)    // 3072

// ---------------------------------------------------------------------------
// Scratch (no allocations allowed)
// ---------------------------------------------------------------------------
__device__ __align__(128) float g_qkv[MROWS * N3D];    // [4096, 3072]
__device__ __align__(128) float g_ao[MROWS * DDIM];    // [4096, 1024]
// attention bf16 hi/lo buffers
__device__ __align__(128) __nv_bfloat16 g_ahi[MROWS * DDIM];   // q hi (head-major)
__device__ __align__(128) __nv_bfloat16 g_alo[MROWS * DDIM];   // q lo
__device__ __align__(128) __nv_bfloat16 g_aohi[MROWS * DDIM];  // k hi
__device__ __align__(128) __nv_bfloat16 g_aolo[MROWS * DDIM];  // k lo
__device__ __align__(128) __nv_bfloat16 g_vth[MROWS * DDIM];   // V^T hi [bh][64][2048]
__device__ __align__(128) __nv_bfloat16 g_vtl[MROWS * DDIM];   // V^T lo
// fp16 GEMM operands
__device__ __align__(128) __half g_ah[MROWS * DDIM];           // activations fp16
__device__ __align__(128) __half g_wqt[N3D * DDIM];            // W_attn^T fp16 [N][K]
__device__ __align__(128) __half g_wpt[DDIM * DDIM];           // W_proj^T fp16 [N][K]

// ---------------------------------------------------------------------------
// Baseline-PTX tensor-core helpers
// ---------------------------------------------------------------------------
__device__ __forceinline__ uint32_t smem_u32(const void* p) {
    uint32_t a;
    asm("{ .reg .u64 t; cvta.to.shared.u64 t, %1; cvt.u32.u64 %0, t; }"
        : "=r"(a) : "l"(p));
    return a;
}
__device__ __forceinline__ void ldsm4(uint32_t r[4], uint32_t addr) {
    asm volatile("ldmatrix.sync.aligned.m8n8.x4.shared.b16 {%0,%1,%2,%3}, [%4];"
                 : "=r"(r[0]), "=r"(r[1]), "=r"(r[2]), "=r"(r[3]) : "r"(addr));
}
// bf16 MMA (attention)
__device__ __forceinline__ void mma16816(float c[4], const uint32_t a[4],
                                         uint32_t b0, uint32_t b1) {
    asm volatile(
        "mma.sync.aligned.m16n8k16.row.col.f32.bf16.bf16.f32 "
        "{%0,%1,%2,%3}, {%4,%5,%6,%7}, {%8,%9}, {%0,%1,%2,%3};"
        : "+f"(c[0]), "+f"(c[1]), "+f"(c[2]), "+f"(c[3])
        : "r"(a[0]), "r"(a[1]), "r"(a[2]), "r"(a[3]), "r"(b0), "r"(b1));
}
// fp16 MMA (projections)
__device__ __forceinline__ void mma16816h(float c[4], const uint32_t a[4],
                                          uint32_t b0, uint32_t b1) {
    asm volatile(
        "mma.sync.aligned.m16n8k16.row.col.f32.f16.f16.f32 "
        "{%0,%1,%2,%3}, {%4,%5,%6,%7}, {%8,%9}, {%0,%1,%2,%3};"
        : "+f"(c[0]), "+f"(c[1]), "+f"(c[2]), "+f"(c[3])
        : "r"(a[0]), "r"(a[1]), "r"(a[2]), "r"(a[3]), "r"(b0), "r"(b1));
}
__device__ __forceinline__ void cp16(uint32_t dst, const void* src) {
    asm volatile("cp.async.cg.shared.global [%0], [%1], 16;"
                 :: "r"(dst), "l"(src) : "memory");
}
#define CP_COMMIT() asm volatile("cp.async.commit_group;" ::: "memory")
#define CP_WAIT1()  asm volatile("cp.async.wait_group 1;" ::: "memory")

__device__ __forceinline__ uint32_t packbf(float x, float y) {
    __nv_bfloat162 t = __floats2bfloat162_rn(x, y);
    return *(uint32_t*)&t;
}

// ---------------------------------------------------------------------------
// fp32 -> fp16 convert (elementwise, vectorized)
// ---------------------------------------------------------------------------
__global__ __launch_bounds__(256) void conv_half(const float* __restrict__ x,
                                                 __half* __restrict__ o, int n4) {
    int i = blockIdx.x * blockDim.x + threadIdx.x;
    if (i >= n4) return;
    float4 v = ((const float4*)x)[i];
    __half2 h0 = __floats2half2_rn(v.x, v.y);
    __half2 h1 = __floats2half2_rn(v.z, v.w);
    ((__half2*)o)[2 * i]     = h0;
    ((__half2*)o)[2 * i + 1] = h1;
}

// Transpose W[K,N] -> out[N,K] fp16
__global__ __launch_bounds__(256) void transpose_half(const float* __restrict__ W,
                                                      __half* __restrict__ T,
                                                      int K, int N) {
    __shared__ float t[32][33];
    int n0 = blockIdx.x * 32, k0 = blockIdx.y * 32;
    int tx = threadIdx.x, ty = threadIdx.y;  // 32 x 8
    #pragma unroll
    for (int i = 0; i < 4; i++)
        t[ty + i * 8][tx] = W[(size_t)(k0 + ty + i * 8) * N + n0 + tx];
    __syncthreads();
    #pragma unroll
    for (int i = 0; i < 4; i++) {
        int r = ty + i * 8;
        T[(size_t)(n0 + r) * K + k0 + tx] = __float2half_rn(t[tx][r]);
    }
}

// ---------------------------------------------------------------------------
// Q/K repack: g_qkv -> head-major [bh][n][64] bf16 hi/lo. Q scaled by 0.125.
// ---------------------------------------------------------------------------
__global__ __launch_bounds__(256) void qk_split(
    __nv_bfloat16* __restrict__ qh, __nv_bfloat16* __restrict__ ql,
    __nv_bfloat16* __restrict__ kh, __nv_bfloat16* __restrict__ kl) {
    int i = blockIdx.x * blockDim.x + threadIdx.x;
    if (i >= MROWS * DDIM / 4) return;
    int row = i >> 8;
    int c4  = i & 255;
    int h   = c4 >> 4;
    int d   = (c4 & 15) * 4;
    int b = row >> 11, n = row & 2047;
    size_t oi = ((size_t)(b * HH + h) * NN + n) * HD + d;

    float4 q = *(const float4*)&g_qkv[(size_t)row * N3D + c4 * 4];
    float4 k = *(const float4*)&g_qkv[(size_t)row * N3D + DDIM + c4 * 4];
    float qa[4] = {q.x * 0.125f, q.y * 0.125f, q.z * 0.125f, q.w * 0.125f};
    float ka[4] = {k.x, k.y, k.z, k.w};
    __nv_bfloat16 qhh[4], qll[4], khh[4], kll[4];
    #pragma unroll
    for (int j = 0; j < 4; j++) {
        qhh[j] = __float2bfloat16(qa[j]);
        qll[j] = __float2bfloat16(qa[j] - __bfloat162float(qhh[j]));
        khh[j] = __float2bfloat16(ka[j]);
        kll[j] = __float2bfloat16(ka[j] - __bfloat162float(khh[j]));
    }
    ((__nv_bfloat162*)(qh + oi))[0] = __nv_bfloat162(qhh[0], qhh[1]);
    ((__nv_bfloat162*)(qh + oi))[1] = __nv_bfloat162(qhh[2], qhh[3]);
    ((__nv_bfloat162*)(ql + oi))[0] = __nv_bfloat162(qll[0], qll[1]);
    ((__nv_bfloat162*)(ql + oi))[1] = __nv_bfloat162(qll[2], qll[3]);
    ((__nv_bfloat162*)(kh + oi))[0] = __nv_bfloat162(khh[0], khh[1]);
    ((__nv_bfloat162*)(kh + oi))[1] = __nv_bfloat162(khh[2], khh[3]);
    ((__nv_bfloat162*)(kl + oi))[0] = __nv_bfloat162(kll[0], kll[1]);
    ((__nv_bfloat162*)(kl + oi))[1] = __nv_bfloat162(kll[2], kll[3]);
}

// ---------------------------------------------------------------------------
// V repack transposed: g_qkv v-part -> [bh][64 d][2048 n] bf16 hi/lo
// ---------------------------------------------------------------------------
__global__ __launch_bounds__(256) void v_splitT(
    __nv_bfloat16* __restrict__ vth, __nv_bfloat16* __restrict__ vtl) {
    __shared__ float t[64][65];
    const int n0 = blockIdx.x * 64;
    const int bh = blockIdx.y;
    const int b = bh >> 4, h = bh & 15;
    const int tid = threadIdx.x;
    const int r16 = tid >> 4;
    const int c16 = tid & 15;

    #pragma unroll
    for (int i = 0; i < 4; i++) {
        int n = i * 16 + r16;
        float4 v = *(const float4*)&g_qkv[(size_t)(b * NN + n0 + n) * N3D
                                          + 2 * DDIM + h * HD + c16 * 4];
        t[n][c16 * 4 + 0] = v.x;
        t[n][c16 * 4 + 1] = v.y;
        t[n][c16 * 4 + 2] = v.z;
        t[n][c16 * 4 + 3] = v.w;
    }
    __syncthreads();
    #pragma unroll
    for (int i = 0; i < 4; i++) {
        int d = i * 16 + r16;
        int n = c16 * 4;
        __nv_bfloat16 hh[4], ll[4];
        #pragma unroll
        for (int j = 0; j < 4; j++) {
            float v = t[n + j][d];
            hh[j] = __float2bfloat16(v);
            ll[j] = __float2bfloat16(v - __bfloat162float(hh[j]));
        }
        size_t oi = ((size_t)bh * HD + d) * NN + n0 + n;
        ((__nv_bfloat162*)(vth + oi))[0] = __nv_bfloat162(hh[0], hh[1]);
        ((__nv_bfloat162*)(vth + oi))[1] = __nv_bfloat162(hh[2], hh[3]);
        ((__nv_bfloat162*)(vtl + oi))[0] = __nv_bfloat162(ll[0], ll[1]);
        ((__nv_bfloat162*)(vtl + oi))[1] = __nv_bfloat162(ll[2], ll[3]);
    }
}

// ---------------------------------------------------------------------------
// fp16 single-product GEMM via mma.sync (unchanged, passing):
// C[M,NTOT] = A[M,1024] @ B^T + bias, B as [NTOT][1024] fp16 k-major.
// ---------------------------------------------------------------------------
#define TILE_B    10240
#define F16_STAGE (2 * TILE_B)    // 20480
#define F16_SMEM  (3 * F16_STAGE) // 61440

template<int NTOT>
__global__ __launch_bounds__(512) void tc_gemm_f16(
    const __half* __restrict__ A, const __half* __restrict__ B,
    const float* __restrict__ bias, float* __restrict__ C)
{
    extern __shared__ char sm[];
    const uint32_t smb = smem_u32(sm);
    const int tid = threadIdx.x;
    const int lane = tid & 31;
    const int wid = tid >> 5;
    const int wm = wid & 3;
    const int wn = wid >> 2;
    const int bm = blockIdx.y * 128;
    const int bn = blockIdx.x * 128;

    float acc[2][4][4];
    #pragma unroll
    for (int i = 0; i < 2; i++)
        #pragma unroll
        for (int j = 0; j < 4; j++)
            #pragma unroll
            for (int k = 0; k < 4; k++) acc[i][j][k] = 0.f;

    const int lrow = tid >> 2;
    const int lc   = tid & 3;
    #define F16_LOAD(stg, k0)                                                     \
        do {                                                                      \
            uint32_t st_ = smb + (stg) * F16_STAGE;                               \
            uint32_t doff_ = (uint32_t)(lrow * 80 + lc * 16);                     \
            cp16(st_ + doff_,          A + (size_t)(bm + lrow) * 1024 + (k0) + lc * 8); \
            cp16(st_ + TILE_B + doff_, B + (size_t)(bn + lrow) * 1024 + (k0) + lc * 8); \
        } while (0)

    const uint32_t a_roff = (uint32_t)((wm * 32 + (lane & 15)) * 80 + (lane >> 4) * 16);
    const uint32_t b_row  = (uint32_t)((lane & 7) | ((lane & 16) >> 1));
    const uint32_t b_roff = (uint32_t)((wn * 32 + b_row) * 80 + ((lane >> 3) & 1) * 16);

    F16_LOAD(0, 0);
    CP_COMMIT();
    F16_LOAD(1, 32);
    CP_COMMIT();

    const int NIT = 1024 / 32;
    int stg = 0;
    for (int it = 0; it < NIT; it++) {
        CP_WAIT1();
        __syncthreads();
        if (it + 2 < NIT) F16_LOAD((stg + 2) % 3, (it + 2) * 32);
        CP_COMMIT();

        const uint32_t sA = smb + stg * F16_STAGE;
        const uint32_t sB = sA + TILE_B;

        #pragma unroll
        for (int ks = 0; ks < 2; ks++) {
            uint32_t af[2][4], bf_[2][4];
            uint32_t ao = a_roff + ks * 32;
            ldsm4(af[0], sA + ao);
            ldsm4(af[1], sA + ao + 16 * 80);
            uint32_t bo = b_roff + ks * 32;
            ldsm4(bf_[0], sB + bo);
            ldsm4(bf_[1], sB + bo + 16 * 80);
            #pragma unroll
            for (int mf = 0; mf < 2; mf++)
                #pragma unroll
                for (int nf = 0; nf < 4; nf++) {
                    int g = nf >> 1, o = (nf & 1) * 2;
                    mma16816h(acc[mf][nf], af[mf], bf_[g][o], bf_[g][o + 1]);
                }
        }
        stg = (stg + 1) % 3;
    }

    #pragma unroll
    for (int nf = 0; nf < 4; nf++) {
        int col = bn + wn * 32 + nf * 8 + (lane & 3) * 2;
        float b0 = __ldg(&bias[col]);
        float b1 = __ldg(&bias[col + 1]);
        #pragma unroll
        for (int mf = 0; mf < 2; mf++) {
            int row0 = bm + wm * 32 + mf * 16 + (lane >> 2);
            float2 v0 = make_float2(acc[mf][nf][0] + b0, acc[mf][nf][1] + b1);
            float2 v1 = make_float2(acc[mf][nf][2] + b0, acc[mf][nf][3] + b1);
            *(float2*)&C[(size_t)row0 * NTOT + col]       = v0;
            *(float2*)&C[(size_t)(row0 + 8) * NTOT + col] = v1;
        }
    }
}

// ---------------------------------------------------------------------------
// Flash attention via mma.sync, bf16x3, 2-stage cp.async K/V pipeline.
// CTA = (128-row q tile, bh). 8 warps x 16 rows. KV tiles of 128.
// Per stage: Kh[128][72] + Kl + Vh[64][136] + Vl (bf16). Two stages.
// ---------------------------------------------------------------------------
#define AT_KSTR 72
#define AT_VSTR 136
#define AT_STAGE_E (2 * 128 * AT_KSTR + 2 * 64 * AT_VSTR)   // 35840 elems
#define AT_STAGE_B (AT_STAGE_E * 2)                         // 71680 bytes
#define ATT_SMEM (2 * AT_STAGE_B)                           // 143360 bytes

__global__ __launch_bounds__(256, 1) void attn_mma(
    const __nv_bfloat16* __restrict__ qh, const __nv_bfloat16* __restrict__ ql,
    const __nv_bfloat16* __restrict__ kh, const __nv_bfloat16* __restrict__ kl,
    const __nv_bfloat16* __restrict__ vth, const __nv_bfloat16* __restrict__ vtl)
{
    extern __shared__ __nv_bfloat16 sb[];
    __nv_bfloat16* sKh = sb;                       // stage-0 pointers
    __nv_bfloat16* sKl = sb + 128 * AT_KSTR;
    const uint32_t aKh = smem_u32(sKh);
    const uint32_t aKl = aKh + 128 * AT_KSTR * 2;
    const uint32_t aVh = aKh + 2 * 128 * AT_KSTR * 2;
    const uint32_t aVl = aVh + 64 * AT_VSTR * 2;

    const int tid = threadIdx.x, lane = tid & 31, w = tid >> 5;
    const int qt = 15 - (int)blockIdx.x;
    const int bh = blockIdx.y;
    const int b = bh >> 4, h = bh & 15;
    const size_t hb = (size_t)bh * (NN * HD);
    const size_t vb = (size_t)bh * (HD * NN);

    const int r8  = tid >> 3, c8 = tid & 7;
    const int r16v = tid >> 4, c16v = tid & 15;
    const uint32_t brow = (uint32_t)((lane & 7) | ((lane & 16) >> 1));
    const uint32_t bcol8 = (uint32_t)(((lane >> 3) & 1) * 8);

    // cp.async tile loader for kv tile kt_ into stage stg_
    #define AT_LOAD(stg_, kt_)                                                    \
        do {                                                                      \
            uint32_t kb_ = (uint32_t)(stg_) * AT_STAGE_B;                         \
            int kv0_ = (kt_) * 128;                                               \
            _Pragma("unroll")                                                     \
            for (int i_ = 0; i_ < 4; i_++) {                                      \
                int r_ = i_ * 32 + r8;                                            \
                size_t g_ = hb + (size_t)(kv0_ + r_) * HD + c8 * 8;               \
                uint32_t so_ = (uint32_t)(r_ * AT_KSTR + c8 * 8) * 2;             \
                cp16(aKh + kb_ + so_, kh + g_);                                   \
                cp16(aKl + kb_ + so_, kl + g_);                                   \
            }                                                                     \
            _Pragma("unroll")                                                     \
            for (int i_ = 0; i_ < 4; i_++) {                                      \
                int d_ = i_ * 16 + r16v;                                          \
                size_t g_ = vb + (size_t)d_ * NN + kv0_ + c16v * 8;               \
                uint32_t so_ = (uint32_t)(d_ * AT_VSTR + c16v * 8) * 2;           \
                cp16(aVh + kb_ + so_, vth + g_);                                  \
                cp16(aVl + kb_ + so_, vtl + g_);                                  \
            }                                                                     \
        } while (0)

    // ---- stage Q into stage-0 K buffers (direct), extract A-frags ----
    #pragma unroll
    for (int i = 0; i < 4; i++) {
        int r = i * 32 + r8;
        size_t g = hb + (size_t)(qt * 128 + r) * HD + c8 * 8;
        *(uint4*)(sKh + r * AT_KSTR + c8 * 8) = *(const uint4*)(qh + g);
        *(uint4*)(sKl + r * AT_KSTR + c8 * 8) = *(const uint4*)(ql + g);
    }
    __syncthreads();
    uint32_t qfh[4][4], qfl[4][4];
    #pragma unroll
    for (int ks = 0; ks < 4; ks++) {
        uint32_t off = (uint32_t)(((w * 16 + (lane & 15)) * AT_KSTR
                                   + (lane >> 4) * 8 + ks * 16) * 2);
        ldsm4(qfh[ks], aKh + off);
        ldsm4(qfl[ks], aKl + off);
    }
    __syncthreads();   // all Q reads done before cp.async overwrites stage 0

    float m0 = -1e30f, m1 = -1e30f, l0 = 0.f, l1 = 0.f;
    float o[8][4];
    #pragma unroll
    for (int i = 0; i < 8; i++)
        #pragma unroll
        for (int j = 0; j < 4; j++) o[i][j] = 0.f;

    const int nkv = qt + 1;
    // prefetch tile 0 into stage 0
    AT_LOAD(0, 0);
    CP_COMMIT();

    for (int kt = 0; kt < nkv; kt++) {
        const int stg = kt & 1;
        // issue next tile load into the other stage (its readers finished
        // at the barrier ending iteration kt-1)
        if (kt + 1 < nkv) AT_LOAD(stg ^ 1, kt + 1);
        CP_COMMIT();
        CP_WAIT1();        // tile kt's group complete (this thread)
        __syncthreads();   // visible to all threads

        const uint32_t kb = (uint32_t)stg * AT_STAGE_B;
        const uint32_t bKh = aKh + kb, bKl = aKl + kb;
        const uint32_t bVh = aVh + kb, bVl = aVl + kb;

        // ---- S = Q K^T (bf16x3) ----
        float s[16][4];
        #pragma unroll
        for (int i = 0; i < 16; i++)
            #pragma unroll
            for (int j = 0; j < 4; j++) s[i][j] = 0.f;

        #pragma unroll
        for (int g = 0; g < 8; g++) {
            #pragma unroll
            for (int ks = 0; ks < 4; ks++) {
                uint32_t bhf[4], blf[4];
                uint32_t off = (uint32_t)((((g * 16) + brow) * AT_KSTR
                                           + bcol8 + ks * 16) * 2);
                ldsm4(bhf, bKh + off);
                ldsm4(blf, bKl + off);
                #pragma unroll
                for (int nf2 = 0; nf2 < 2; nf2++) {
                    int nf = g * 2 + nf2, oo = nf2 * 2;
                    mma16816(s[nf], qfh[ks], bhf[oo], bhf[oo + 1]);
                    mma16816(s[nf], qfh[ks], blf[oo], blf[oo + 1]);
                    mma16816(s[nf], qfl[ks], bhf[oo], bhf[oo + 1]);
                }
            }
        }

        // ---- causal mask on diagonal tile ----
        if (kt == qt) {
            int row0 = w * 16 + (lane >> 2);
            #pragma unroll
            for (int nf = 0; nf < 16; nf++) {
                int col = nf * 8 + (lane & 3) * 2;
                if (col > row0)     s[nf][0] = -1e30f;
                if (col + 1 > row0) s[nf][1] = -1e30f;
                if (col > row0 + 8)     s[nf][2] = -1e30f;
                if (col + 1 > row0 + 8) s[nf][3] = -1e30f;
            }
        }

        // ---- online softmax ----
        float mt0 = -1e30f, mt1 = -1e30f;
        #pragma unroll
        for (int nf = 0; nf < 16; nf++) {
            mt0 = fmaxf(mt0, fmaxf(s[nf][0], s[nf][1]));
            mt1 = fmaxf(mt1, fmaxf(s[nf][2], s[nf][3]));
        }
        mt0 = fmaxf(mt0, __shfl_xor_sync(0xffffffffu, mt0, 1));
        mt0 = fmaxf(mt0, __shfl_xor_sync(0xffffffffu, mt0, 2));
        mt1 = fmaxf(mt1, __shfl_xor_sync(0xffffffffu, mt1, 1));
        mt1 = fmaxf(mt1, __shfl_xor_sync(0xffffffffu, mt1, 2));
        float mn0 = fmaxf(m0, mt0), mn1 = fmaxf(m1, mt1);
        float cr0 = __expf(m0 - mn0), cr1 = __expf(m1 - mn1);
        float rs0 = 0.f, rs1 = 0.f;
        #pragma unroll
        for (int nf = 0; nf < 16; nf++) {
            s[nf][0] = __expf(s[nf][0] - mn0);
            s[nf][1] = __expf(s[nf][1] - mn0);
            s[nf][2] = __expf(s[nf][2] - mn1);
            s[nf][3] = __expf(s[nf][3] - mn1);
            rs0 += s[nf][0] + s[nf][1];
            rs1 += s[nf][2] + s[nf][3];
        }
        rs0 += __shfl_xor_sync(0xffffffffu, rs0, 1);
        rs0 += __shfl_xor_sync(0xffffffffu, rs0, 2);
        rs1 += __shfl_xor_sync(0xffffffffu, rs1, 1);
        rs1 += __shfl_xor_sync(0xffffffffu, rs1, 2);
        l0 = l0 * cr0 + rs0;
        l1 = l1 * cr1 + rs1;
        m0 = mn0; m1 = mn1;
        #pragma unroll
        for (int nf = 0; nf < 8; nf++) {
            o[nf][0] *= cr0; o[nf][1] *= cr0;
            o[nf][2] *= cr1; o[nf][3] *= cr1;
        }

        // ---- O += P V (bf16x3, P packed on the fly) ----
        #pragma unroll
        for (int ks2 = 0; ks2 < 8; ks2++) {
            uint32_t pah[4], pal[4];
            {
                const float* s0 = s[2 * ks2];
                const float* s1 = s[2 * ks2 + 1];
                float h00 = __bfloat162float(__float2bfloat16(s0[0]));
                float h01 = __bfloat162float(__float2bfloat16(s0[1]));
                float h02 = __bfloat162float(__float2bfloat16(s0[2]));
                float h03 = __bfloat162float(__float2bfloat16(s0[3]));
                float h10 = __bfloat162float(__float2bfloat16(s1[0]));
                float h11 = __bfloat162float(__float2bfloat16(s1[1]));
                float h12 = __bfloat162float(__float2bfloat16(s1[2]));
                float h13 = __bfloat162float(__float2bfloat16(s1[3]));
                pah[0] = packbf(h00, h01);
                pah[1] = packbf(h02, h03);
                pah[2] = packbf(h10, h11);
                pah[3] = packbf(h12, h13);
                pal[0] = packbf(s0[0] - h00, s0[1] - h01);
                pal[1] = packbf(s0[2] - h02, s0[3] - h03);
                pal[2] = packbf(s1[0] - h10, s1[1] - h11);
                pal[3] = packbf(s1[2] - h12, s1[3] - h13);
            }
            #pragma unroll
            for (int g = 0; g < 4; g++) {
                uint32_t vhf[4], vlf[4];
                uint32_t off = (uint32_t)((((g * 16) + brow) * AT_VSTR
                                           + bcol8 + ks2 * 16) * 2);
                ldsm4(vhf, bVh + off);
                ldsm4(vlf, bVl + off);
                #pragma unroll
                for (int nf2 = 0; nf2 < 2; nf2++) {
                    int nf = g * 2 + nf2, oo = nf2 * 2;
                    mma16816(o[nf], pah, vhf[oo], vhf[oo + 1]);
                    mma16816(o[nf], pah, vlf[oo], vlf[oo + 1]);
                    mma16816(o[nf], pal, vhf[oo], vhf[oo + 1]);
                }
            }
        }
        __syncthreads();   // all reads of stage `stg` done before it is refilled
    }

    float inv0 = 1.f / l0, inv1 = 1.f / l1;
    const int row0 = b * NN + qt * 128 + w * 16 + (lane >> 2);
    #pragma unroll
    for (int nf = 0; nf < 8; nf++) {
        int col = h * HD + nf * 8 + (lane & 3) * 2;
        *(float2*)&g_ao[(size_t)row0 * DDIM + col] =
            make_float2(o[nf][0] * inv0, o[nf][1] * inv0);
        *(float2*)&g_ao[(size_t)(row0 + 8) * DDIM + col] =
            make_float2(o[nf][2] * inv1, o[nf][3] * inv1);
    }
}

// ---------------------------------------------------------------------------
// Launch
// ---------------------------------------------------------------------------
extern "C" void kernel_launch(void* const* d_in, const int* in_sizes, int n_in,
                              void* d_out, int out_size) {
    const float* hs     = (const float*)d_in[0];
    const float* W_attn = (const float*)d_in[1];
    const float* b_attn = (const float*)d_in[2];
    const float* W_proj = (const float*)d_in[3];
    const float* b_proj = (const float*)d_in[4];
    float* out = (float*)d_out;

    cudaFuncSetAttribute(attn_mma,
                         cudaFuncAttributeMaxDynamicSharedMemorySize, ATT_SMEM);
    cudaFuncSetAttribute(tc_gemm_f16<N3D>,
                         cudaFuncAttributeMaxDynamicSharedMemorySize, F16_SMEM);
    cudaFuncSetAttribute(tc_gemm_f16<DDIM>,
                         cudaFuncAttributeMaxDynamicSharedMemorySize, F16_SMEM);

    __nv_bfloat16 *ahi, *alo, *aohi, *aolo, *vth, *vtl;
    __half *ah, *wqt, *wpt;
    float *qkv_p, *ao_p;
    cudaGetSymbolAddress((void**)&ahi,  g_ahi);
    cudaGetSymbolAddress((void**)&alo,  g_alo);
    cudaGetSymbolAddress((void**)&aohi, g_aohi);
    cudaGetSymbolAddress((void**)&aolo, g_aolo);
    cudaGetSymbolAddress((void**)&vth,  g_vth);
    cudaGetSymbolAddress((void**)&vtl,  g_vtl);
    cudaGetSymbolAddress((void**)&ah,   g_ah);
    cudaGetSymbolAddress((void**)&wqt,  g_wqt);
    cudaGetSymbolAddress((void**)&wpt,  g_wpt);
    cudaGetSymbolAddress((void**)&qkv_p, g_qkv);
    cudaGetSymbolAddress((void**)&ao_p,  g_ao);

    dim3 tt(32, 8);
    // 1) convert hidden_states to fp16
    conv_half<<<(MROWS * DDIM / 4 + 255) / 256, 256>>>(hs, ah, MROWS * DDIM / 4);
    // 2) transpose weights to fp16 [N][K]
    transpose_half<<<dim3(N3D / 32, DDIM / 32), tt>>>(W_attn, wqt, DDIM, N3D);
    transpose_half<<<dim3(DDIM / 32, DDIM / 32), tt>>>(W_proj, wpt, DDIM, DDIM);
    // 3) QKV projection (fp16 tensor cores, single product)
    tc_gemm_f16<N3D><<<dim3(N3D / 128, MROWS / 128), 512, F16_SMEM>>>(
        ah, wqt, b_attn, qkv_p);
    // 4) repack q/k (head-major, q pre-scaled) and v (transposed) for attention
    qk_split<<<(MROWS * DDIM / 4 + 255) / 256, 256>>>(ahi, alo, aohi, aolo);
    v_splitT<<<dim3(NN / 64, BB * HH), 256>>>(vth, vtl);
    // 5) causal flash attention on tensor cores (bf16x3, cp.async pipelined)
    attn_mma<<<dim3(NN / 128, BB * HH), 256, ATT_SMEM>>>(ahi, alo, aohi, aolo, vth, vtl);
    // 6) convert attention output to fp16
    conv_half<<<(MROWS * DDIM / 4 + 255) / 256, 256>>>(ao_p, ah, MROWS * DDIM / 4);
    // 7) output projection (fp16 tensor cores, single product)
    tc_gemm_f16<DDIM><<<dim3(DDIM / 128, MROWS / 128), 512, F16_SMEM>>>(
        ah, wpt, b_proj, out);
}

// round 11
// speedup vs baseline: 5.3721x; 1.2751x over previous
#include <cuda_runtime.h>
#include <cuda_bf16.h>
#include <cuda_fp16.h>
#include <cstdint>

// Problem constants
#define BB 2
#define NN 2048
#define DDIM 1024
#define HH 16
#define HD 64
#define MROWS (BB * NN)   // 4096
#define N3D (3 * DDIM)    // 3072

// ---------------------------------------------------------------------------
// Scratch (no allocations allowed)
// ---------------------------------------------------------------------------
__device__ __align__(128) float g_qkv[MROWS * N3D];    // [4096, 3072]
__device__ __align__(128) float g_ao[MROWS * DDIM];    // [4096, 1024]
// fp16 GEMM operands
__device__ __align__(128) __half g_ah[MROWS * DDIM];   // activations fp16
__device__ __align__(128) __half g_wqt[N3D * DDIM];    // W_attn^T fp16 [N][K]
__device__ __align__(128) __half g_wpt[DDIM * DDIM];   // W_proj^T fp16 [N][K]
// fp16 attention operands
__device__ __align__(128) __half g_qf[MROWS * DDIM];   // q fp16 head-major, prescaled
__device__ __align__(128) __half g_kf[MROWS * DDIM];   // k fp16 head-major
__device__ __align__(128) __half g_vtf[MROWS * DDIM];  // V^T fp16 [bh][64][2048]

// ---------------------------------------------------------------------------
// Baseline-PTX tensor-core helpers
// ---------------------------------------------------------------------------
__device__ __forceinline__ uint32_t smem_u32(const void* p) {
    uint32_t a;
    asm("{ .reg .u64 t; cvta.to.shared.u64 t, %1; cvt.u32.u64 %0, t; }"
        : "=r"(a) : "l"(p));
    return a;
}
__device__ __forceinline__ void ldsm4(uint32_t r[4], uint32_t addr) {
    asm volatile("ldmatrix.sync.aligned.m8n8.x4.shared.b16 {%0,%1,%2,%3}, [%4];"
                 : "=r"(r[0]), "=r"(r[1]), "=r"(r[2]), "=r"(r[3]) : "r"(addr));
}
// fp16 MMA
__device__ __forceinline__ void mma16816h(float c[4], const uint32_t a[4],
                                          uint32_t b0, uint32_t b1) {
    asm volatile(
        "mma.sync.aligned.m16n8k16.row.col.f32.f16.f16.f32 "
        "{%0,%1,%2,%3}, {%4,%5,%6,%7}, {%8,%9}, {%0,%1,%2,%3};"
        : "+f"(c[0]), "+f"(c[1]), "+f"(c[2]), "+f"(c[3])
        : "r"(a[0]), "r"(a[1]), "r"(a[2]), "r"(a[3]), "r"(b0), "r"(b1));
}
__device__ __forceinline__ void cp16(uint32_t dst, const void* src) {
    asm volatile("cp.async.cg.shared.global [%0], [%1], 16;"
                 :: "r"(dst), "l"(src) : "memory");
}
#define CP_COMMIT() asm volatile("cp.async.commit_group;" ::: "memory")
#define CP_WAIT1()  asm volatile("cp.async.wait_group 1;" ::: "memory")

__device__ __forceinline__ uint32_t packhf(float x, float y) {
    __half2 t = __floats2half2_rn(x, y);
    return *(uint32_t*)&t;
}

// ---------------------------------------------------------------------------
// fp32 -> fp16 convert (elementwise, vectorized)
// ---------------------------------------------------------------------------
__global__ __launch_bounds__(256) void conv_half(const float* __restrict__ x,
                                                 __half* __restrict__ o, int n4) {
    int i = blockIdx.x * blockDim.x + threadIdx.x;
    if (i >= n4) return;
    float4 v = ((const float4*)x)[i];
    ((__half2*)o)[2 * i]     = __floats2half2_rn(v.x, v.y);
    ((__half2*)o)[2 * i + 1] = __floats2half2_rn(v.z, v.w);
}

// Transpose W[K,N] -> out[N,K] fp16
__global__ __launch_bounds__(256) void transpose_half(const float* __restrict__ W,
                                                      __half* __restrict__ T,
                                                      int K, int N) {
    __shared__ float t[32][33];
    int n0 = blockIdx.x * 32, k0 = blockIdx.y * 32;
    int tx = threadIdx.x, ty = threadIdx.y;  // 32 x 8
    #pragma unroll
    for (int i = 0; i < 4; i++)
        t[ty + i * 8][tx] = W[(size_t)(k0 + ty + i * 8) * N + n0 + tx];
    __syncthreads();
    #pragma unroll
    for (int i = 0; i < 4; i++) {
        int r = ty + i * 8;
        T[(size_t)(n0 + r) * K + k0 + tx] = __float2half_rn(t[tx][r]);
    }
}

// ---------------------------------------------------------------------------
// Q/K repack: g_qkv -> head-major [bh][n][64] fp16. Q scaled by 0.125.
// ---------------------------------------------------------------------------
__global__ __launch_bounds__(256) void qk_half(
    __half* __restrict__ qf, __half* __restrict__ kf) {
    int i = blockIdx.x * blockDim.x + threadIdx.x;
    if (i >= MROWS * DDIM / 4) return;
    int row = i >> 8;
    int c4  = i & 255;
    int h   = c4 >> 4;
    int d   = (c4 & 15) * 4;
    int b = row >> 11, n = row & 2047;
    size_t oi = ((size_t)(b * HH + h) * NN + n) * HD + d;

    float4 q = *(const float4*)&g_qkv[(size_t)row * N3D + c4 * 4];
    float4 k = *(const float4*)&g_qkv[(size_t)row * N3D + DDIM + c4 * 4];
    ((__half2*)(qf + oi))[0] = __floats2half2_rn(q.x * 0.125f, q.y * 0.125f);
    ((__half2*)(qf + oi))[1] = __floats2half2_rn(q.z * 0.125f, q.w * 0.125f);
    ((__half2*)(kf + oi))[0] = __floats2half2_rn(k.x, k.y);
    ((__half2*)(kf + oi))[1] = __floats2half2_rn(k.z, k.w);
}

// ---------------------------------------------------------------------------
// V repack transposed: g_qkv v-part -> [bh][64 d][2048 n] fp16
// ---------------------------------------------------------------------------
__global__ __launch_bounds__(256) void v_halfT(__half* __restrict__ vtf) {
    __shared__ float t[64][65];
    const int n0 = blockIdx.x * 64;
    const int bh = blockIdx.y;
    const int b = bh >> 4, h = bh & 15;
    const int tid = threadIdx.x;
    const int r16 = tid >> 4;
    const int c16 = tid & 15;

    #pragma unroll
    for (int i = 0; i < 4; i++) {
        int n = i * 16 + r16;
        float4 v = *(const float4*)&g_qkv[(size_t)(b * NN + n0 + n) * N3D
                                          + 2 * DDIM + h * HD + c16 * 4];
        t[n][c16 * 4 + 0] = v.x;
        t[n][c16 * 4 + 1] = v.y;
        t[n][c16 * 4 + 2] = v.z;
        t[n][c16 * 4 + 3] = v.w;
    }
    __syncthreads();
    #pragma unroll
    for (int i = 0; i < 4; i++) {
        int d = i * 16 + r16;
        int n = c16 * 4;
        size_t oi = ((size_t)bh * HD + d) * NN + n0 + n;
        ((__half2*)(vtf + oi))[0] = __floats2half2_rn(t[n + 0][d], t[n + 1][d]);
        ((__half2*)(vtf + oi))[1] = __floats2half2_rn(t[n + 2][d], t[n + 3][d]);
    }
}

// ---------------------------------------------------------------------------
// fp16 single-product GEMM via mma.sync (unchanged, passing):
// C[M,NTOT] = A[M,1024] @ B^T + bias, B as [NTOT][1024] fp16 k-major.
// ---------------------------------------------------------------------------
#define TILE_B    10240
#define F16_STAGE (2 * TILE_B)    // 20480
#define F16_SMEM  (3 * F16_STAGE) // 61440

template<int NTOT>
__global__ __launch_bounds__(512) void tc_gemm_f16(
    const __half* __restrict__ A, const __half* __restrict__ B,
    const float* __restrict__ bias, float* __restrict__ C)
{
    extern __shared__ char sm[];
    const uint32_t smb = smem_u32(sm);
    const int tid = threadIdx.x;
    const int lane = tid & 31;
    const int wid = tid >> 5;
    const int wm = wid & 3;
    const int wn = wid >> 2;
    const int bm = blockIdx.y * 128;
    const int bn = blockIdx.x * 128;

    float acc[2][4][4];
    #pragma unroll
    for (int i = 0; i < 2; i++)
        #pragma unroll
        for (int j = 0; j < 4; j++)
            #pragma unroll
            for (int k = 0; k < 4; k++) acc[i][j][k] = 0.f;

    const int lrow = tid >> 2;
    const int lc   = tid & 3;
    #define F16_LOAD(stg, k0)                                                     \
        do {                                                                      \
            uint32_t st_ = smb + (stg) * F16_STAGE;                               \
            uint32_t doff_ = (uint32_t)(lrow * 80 + lc * 16);                     \
            cp16(st_ + doff_,          A + (size_t)(bm + lrow) * 1024 + (k0) + lc * 8); \
            cp16(st_ + TILE_B + doff_, B + (size_t)(bn + lrow) * 1024 + (k0) + lc * 8); \
        } while (0)

    const uint32_t a_roff = (uint32_t)((wm * 32 + (lane & 15)) * 80 + (lane >> 4) * 16);
    const uint32_t b_row  = (uint32_t)((lane & 7) | ((lane & 16) >> 1));
    const uint32_t b_roff = (uint32_t)((wn * 32 + b_row) * 80 + ((lane >> 3) & 1) * 16);

    F16_LOAD(0, 0);
    CP_COMMIT();
    F16_LOAD(1, 32);
    CP_COMMIT();

    const int NIT = 1024 / 32;
    int stg = 0;
    for (int it = 0; it < NIT; it++) {
        CP_WAIT1();
        __syncthreads();
        if (it + 2 < NIT) F16_LOAD((stg + 2) % 3, (it + 2) * 32);
        CP_COMMIT();

        const uint32_t sA = smb + stg * F16_STAGE;
        const uint32_t sB = sA + TILE_B;

        #pragma unroll
        for (int ks = 0; ks < 2; ks++) {
            uint32_t af[2][4], bf_[2][4];
            uint32_t ao = a_roff + ks * 32;
            ldsm4(af[0], sA + ao);
            ldsm4(af[1], sA + ao + 16 * 80);
            uint32_t bo = b_roff + ks * 32;
            ldsm4(bf_[0], sB + bo);
            ldsm4(bf_[1], sB + bo + 16 * 80);
            #pragma unroll
            for (int mf = 0; mf < 2; mf++)
                #pragma unroll
                for (int nf = 0; nf < 4; nf++) {
                    int g = nf >> 1, o = (nf & 1) * 2;
                    mma16816h(acc[mf][nf], af[mf], bf_[g][o], bf_[g][o + 1]);
                }
        }
        stg = (stg + 1) % 3;
    }

    #pragma unroll
    for (int nf = 0; nf < 4; nf++) {
        int col = bn + wn * 32 + nf * 8 + (lane & 3) * 2;
        float b0 = __ldg(&bias[col]);
        float b1 = __ldg(&bias[col + 1]);
        #pragma unroll
        for (int mf = 0; mf < 2; mf++) {
            int row0 = bm + wm * 32 + mf * 16 + (lane >> 2);
            float2 v0 = make_float2(acc[mf][nf][0] + b0, acc[mf][nf][1] + b1);
            float2 v1 = make_float2(acc[mf][nf][2] + b0, acc[mf][nf][3] + b1);
            *(float2*)&C[(size_t)row0 * NTOT + col]       = v0;
            *(float2*)&C[(size_t)(row0 + 8) * NTOT + col] = v1;
        }
    }
}

// ---------------------------------------------------------------------------
// Flash attention via fp16 mma.sync:
//   S = QK^T   fp16 single product (1 MMA per frag-pair)
//   O += P V   P fp16 hi/lo (2 products), V fp16 single
// CTA = (128-row q tile, bh). 8 warps x 16 rows. KV tiles of 128.
// 2-stage cp.async K/V pipeline. Per stage: K[128][72] + V[64][136] fp16.
// ---------------------------------------------------------------------------
#define AT_KSTR 72
#define AT_VSTR 136
#define AT_K_B  (128 * AT_KSTR * 2)                 // 18432 bytes
#define AT_V_B  (64 * AT_VSTR * 2)                  // 17408 bytes
#define AT_STAGE_B (AT_K_B + AT_V_B)                // 35840 bytes
#define ATT_SMEM (2 * AT_STAGE_B)                   // 71680 bytes

__global__ __launch_bounds__(256, 1) void attn_mma(
    const __half* __restrict__ qf, const __half* __restrict__ kf,
    const __half* __restrict__ vtf)
{
    extern __shared__ __half sbh[];
    __half* sK0 = sbh;                               // stage-0 K (also Q staging)
    const uint32_t aK = smem_u32(sK0);
    const uint32_t aV = aK + AT_K_B;

    const int tid = threadIdx.x, lane = tid & 31, w = tid >> 5;
    const int qt = 15 - (int)blockIdx.x;             // heavy tiles first
    const int bh = blockIdx.y;
    const int b = bh >> 4, h = bh & 15;
    const size_t hb = (size_t)bh * (NN * HD);
    const size_t vb = (size_t)bh * (HD * NN);

    const int r8  = tid >> 3, c8 = tid & 7;
    const int r16v = tid >> 4, c16v = tid & 15;
    const uint32_t brow = (uint32_t)((lane & 7) | ((lane & 16) >> 1));
    const uint32_t bcol8 = (uint32_t)(((lane >> 3) & 1) * 8);

    #define AT_LOAD(stg_, kt_)                                                    \
        do {                                                                      \
            uint32_t kb_ = (uint32_t)(stg_) * AT_STAGE_B;                         \
            int kv0_ = (kt_) * 128;                                               \
            _Pragma("unroll")                                                     \
            for (int i_ = 0; i_ < 4; i_++) {                                      \
                int r_ = i_ * 32 + r8;                                            \
                cp16(aK + kb_ + (uint32_t)(r_ * AT_KSTR + c8 * 8) * 2,            \
                     kf + hb + (size_t)(kv0_ + r_) * HD + c8 * 8);                \
            }                                                                     \
            _Pragma("unroll")                                                     \
            for (int i_ = 0; i_ < 4; i_++) {                                      \
                int d_ = i_ * 16 + r16v;                                          \
                cp16(aV + kb_ + (uint32_t)(d_ * AT_VSTR + c16v * 8) * 2,          \
                     vtf + vb + (size_t)d_ * NN + kv0_ + c16v * 8);               \
            }                                                                     \
        } while (0)

    // ---- stage Q into stage-0 K buffer, extract A-frags ----
    #pragma unroll
    for (int i = 0; i < 4; i++) {
        int r = i * 32 + r8;
        size_t g = hb + (size_t)(qt * 128 + r) * HD + c8 * 8;
        *(uint4*)(sK0 + r * AT_KSTR + c8 * 8) = *(const uint4*)(qf + g);
    }
    __syncthreads();
    uint32_t qfr[4][4];
    #pragma unroll
    for (int ks = 0; ks < 4; ks++) {
        uint32_t off = (uint32_t)(((w * 16 + (lane & 15)) * AT_KSTR
                                   + (lane >> 4) * 8 + ks * 16) * 2);
        ldsm4(qfr[ks], aK + off);
    }
    __syncthreads();   // Q reads done before cp.async overwrites stage 0

    float m0 = -1e30f, m1 = -1e30f, l0 = 0.f, l1 = 0.f;
    float o[8][4];
    #pragma unroll
    for (int i = 0; i < 8; i++)
        #pragma unroll
        for (int j = 0; j < 4; j++) o[i][j] = 0.f;

    const int nkv = qt + 1;
    AT_LOAD(0, 0);
    CP_COMMIT();

    for (int kt = 0; kt < nkv; kt++) {
        const int stg = kt & 1;
        if (kt + 1 < nkv) AT_LOAD(stg ^ 1, kt + 1);
        CP_COMMIT();
        CP_WAIT1();
        __syncthreads();

        const uint32_t kb = (uint32_t)stg * AT_STAGE_B;
        const uint32_t bK = aK + kb, bV = aV + kb;

        // ---- S = Q K^T (fp16 single) ----
        float s[16][4];
        #pragma unroll
        for (int i = 0; i < 16; i++)
            #pragma unroll
            for (int j = 0; j < 4; j++) s[i][j] = 0.f;

        #pragma unroll
        for (int g = 0; g < 8; g++) {
            #pragma unroll
            for (int ks = 0; ks < 4; ks++) {
                uint32_t kfr[4];
                uint32_t off = (uint32_t)((((g * 16) + brow) * AT_KSTR
                                           + bcol8 + ks * 16) * 2);
                ldsm4(kfr, bK + off);
                #pragma unroll
                for (int nf2 = 0; nf2 < 2; nf2++)
                    mma16816h(s[g * 2 + nf2], qfr[ks], kfr[nf2 * 2], kfr[nf2 * 2 + 1]);
            }
        }

        // ---- causal mask on diagonal tile ----
        if (kt == qt) {
            int row0 = w * 16 + (lane >> 2);
            #pragma unroll
            for (int nf = 0; nf < 16; nf++) {
                int col = nf * 8 + (lane & 3) * 2;
                if (col > row0)     s[nf][0] = -1e30f;
                if (col + 1 > row0) s[nf][1] = -1e30f;
                if (col > row0 + 8)     s[nf][2] = -1e30f;
                if (col + 1 > row0 + 8) s[nf][3] = -1e30f;
            }
        }

        // ---- online softmax ----
        float mt0 = -1e30f, mt1 = -1e30f;
        #pragma unroll
        for (int nf = 0; nf < 16; nf++) {
            mt0 = fmaxf(mt0, fmaxf(s[nf][0], s[nf][1]));
            mt1 = fmaxf(mt1, fmaxf(s[nf][2], s[nf][3]));
        }
        mt0 = fmaxf(mt0, __shfl_xor_sync(0xffffffffu, mt0, 1));
        mt0 = fmaxf(mt0, __shfl_xor_sync(0xffffffffu, mt0, 2));
        mt1 = fmaxf(mt1, __shfl_xor_sync(0xffffffffu, mt1, 1));
        mt1 = fmaxf(mt1, __shfl_xor_sync(0xffffffffu, mt1, 2));
        float mn0 = fmaxf(m0, mt0), mn1 = fmaxf(m1, mt1);
        float cr0 = __expf(m0 - mn0), cr1 = __expf(m1 - mn1);
        float rs0 = 0.f, rs1 = 0.f;
        #pragma unroll
        for (int nf = 0; nf < 16; nf++) {
            s[nf][0] = __expf(s[nf][0] - mn0);
            s[nf][1] = __expf(s[nf][1] - mn0);
            s[nf][2] = __expf(s[nf][2] - mn1);
            s[nf][3] = __expf(s[nf][3] - mn1);
            rs0 += s[nf][0] + s[nf][1];
            rs1 += s[nf][2] + s[nf][3];
        }
        rs0 += __shfl_xor_sync(0xffffffffu, rs0, 1);
        rs0 += __shfl_xor_sync(0xffffffffu, rs0, 2);
        rs1 += __shfl_xor_sync(0xffffffffu, rs1, 1);
        rs1 += __shfl_xor_sync(0xffffffffu, rs1, 2);
        l0 = l0 * cr0 + rs0;
        l1 = l1 * cr1 + rs1;
        m0 = mn0; m1 = mn1;
        #pragma unroll
        for (int nf = 0; nf < 8; nf++) {
            o[nf][0] *= cr0; o[nf][1] *= cr0;
            o[nf][2] *= cr1; o[nf][3] *= cr1;
        }

        // ---- O += P V : P fp16 hi/lo, V fp16 single ----
        #pragma unroll
        for (int ks2 = 0; ks2 < 8; ks2++) {
            uint32_t pah[4], pal[4];
            {
                const float* s0 = s[2 * ks2];
                const float* s1 = s[2 * ks2 + 1];
                float h00 = __half2float(__float2half_rn(s0[0]));
                float h01 = __half2float(__float2half_rn(s0[1]));
                float h02 = __half2float(__float2half_rn(s0[2]));
                float h03 = __half2float(__float2half_rn(s0[3]));
                float h10 = __half2float(__float2half_rn(s1[0]));
                float h11 = __half2float(__float2half_rn(s1[1]));
                float h12 = __half2float(__float2half_rn(s1[2]));
                float h13 = __half2float(__float2half_rn(s1[3]));
                pah[0] = packhf(h00, h01);
                pah[1] = packhf(h02, h03);
                pah[2] = packhf(h10, h11);
                pah[3] = packhf(h12, h13);
                pal[0] = packhf(s0[0] - h00, s0[1] - h01);
                pal[1] = packhf(s0[2] - h02, s0[3] - h03);
                pal[2] = packhf(s1[0] - h10, s1[1] - h11);
                pal[3] = packhf(s1[2] - h12, s1[3] - h13);
            }
            #pragma unroll
            for (int g = 0; g < 4; g++) {
                uint32_t vfr[4];
                uint32_t off = (uint32_t)((((g * 16) + brow) * AT_VSTR
                                           + bcol8 + ks2 * 16) * 2);
                ldsm4(vfr, bV + off);
                #pragma unroll
                for (int nf2 = 0; nf2 < 2; nf2++) {
                    int nf = g * 2 + nf2, oo = nf2 * 2;
                    mma16816h(o[nf], pah, vfr[oo], vfr[oo + 1]);
                    mma16816h(o[nf], pal, vfr[oo], vfr[oo + 1]);
                }
            }
        }
        __syncthreads();   // all reads of stage `stg` done before refill
    }

    float inv0 = 1.f / l0, inv1 = 1.f / l1;
    const int row0 = b * NN + qt * 128 + w * 16 + (lane >> 2);
    #pragma unroll
    for (int nf = 0; nf < 8; nf++) {
        int col = h * HD + nf * 8 + (lane & 3) * 2;
        *(float2*)&g_ao[(size_t)row0 * DDIM + col] =
            make_float2(o[nf][0] * inv0, o[nf][1] * inv0);
        *(float2*)&g_ao[(size_t)(row0 + 8) * DDIM + col] =
            make_float2(o[nf][2] * inv1, o[nf][3] * inv1);
    }
}

// ---------------------------------------------------------------------------
// Launch
// ---------------------------------------------------------------------------
extern "C" void kernel_launch(void* const* d_in, const int* in_sizes, int n_in,
                              void* d_out, int out_size) {
    const float* hs     = (const float*)d_in[0];
    const float* W_attn = (const float*)d_in[1];
    const float* b_attn = (const float*)d_in[2];
    const float* W_proj = (const float*)d_in[3];
    const float* b_proj = (const float*)d_in[4];
    float* out = (float*)d_out;

    cudaFuncSetAttribute(attn_mma,
                         cudaFuncAttributeMaxDynamicSharedMemorySize, ATT_SMEM);
    cudaFuncSetAttribute(tc_gemm_f16<N3D>,
                         cudaFuncAttributeMaxDynamicSharedMemorySize, F16_SMEM);
    cudaFuncSetAttribute(tc_gemm_f16<DDIM>,
                         cudaFuncAttributeMaxDynamicSharedMemorySize, F16_SMEM);

    __half *ah, *wqt, *wpt, *qf, *kf, *vtf;
    float *qkv_p, *ao_p;
    cudaGetSymbolAddress((void**)&ah,   g_ah);
    cudaGetSymbolAddress((void**)&wqt,  g_wqt);
    cudaGetSymbolAddress((void**)&wpt,  g_wpt);
    cudaGetSymbolAddress((void**)&qf,   g_qf);
    cudaGetSymbolAddress((void**)&kf,   g_kf);
    cudaGetSymbolAddress((void**)&vtf,  g_vtf);
    cudaGetSymbolAddress((void**)&qkv_p, g_qkv);
    cudaGetSymbolAddress((void**)&ao_p,  g_ao);

    dim3 tt(32, 8);
    // 1) convert hidden_states to fp16
    conv_half<<<(MROWS * DDIM / 4 + 255) / 256, 256>>>(hs, ah, MROWS * DDIM / 4);
    // 2) transpose weights to fp16 [N][K]
    transpose_half<<<dim3(N3D / 32, DDIM / 32), tt>>>(W_attn, wqt, DDIM, N3D);
    transpose_half<<<dim3(DDIM / 32, DDIM / 32), tt>>>(W_proj, wpt, DDIM, DDIM);
    // 3) QKV projection (fp16 tensor cores, single product)
    tc_gemm_f16<N3D><<<dim3(N3D / 128, MROWS / 128), 512, F16_SMEM>>>(
        ah, wqt, b_attn, qkv_p);
    // 4) repack q/k (head-major fp16, q pre-scaled) and v (transposed fp16)
    qk_half<<<(MROWS * DDIM / 4 + 255) / 256, 256>>>(qf, kf);
    v_halfT<<<dim3(NN / 64, BB * HH), 256>>>(vtf);
    // 5) causal flash attention (fp16 tensor cores)
    attn_mma<<<dim3(NN / 128, BB * HH), 256, ATT_SMEM>>>(qf, kf, vtf);
    // 6) convert attention output to fp16
    conv_half<<<(MROWS * DDIM / 4 + 255) / 256, 256>>>(ao_p, ah, MROWS * DDIM / 4);
    // 7) output projection (fp16 tensor cores, single product)
    tc_gemm_f16<DDIM><<<dim3(DDIM / 128, MROWS / 128), 512, F16_SMEM>>>(
        ah, wpt, b_proj, out);
}